// round 13
// baseline (speedup 1.0000x reference)
#include <cuda_runtime.h>
#include <math.h>
#include <stdint.h>

// ---------------------------------------------------------------------------
// Problem constants
// ---------------------------------------------------------------------------
#define BB 2
#define SS 2048
#define DD 1024
#define HH 16
#define DKK 64
#define DFF 4096
#define WINDOW 128
#define NGLOBAL 16
#define MM (BB * SS)   // 4096 rows

// ---------------------------------------------------------------------------
// Scratch (device globals; no allocation allowed)
// ---------------------------------------------------------------------------
__device__ float g_xn  [MM * DD];
__device__ float g_qkv [MM * 3 * DD];
__device__ float g_att [MM * DD];
__device__ float g_x1  [MM * DD];
__device__ float g_xn2 [MM * DD];
__device__ float g_h   [MM * DFF];
__device__ float g_wqkv[3 * DD * DD];   // transposed [3072][1024]
__device__ float g_wo  [DD * DD];       // transposed [1024][1024]
__device__ float g_w1  [DFF * DD];      // transposed [4096][1024]
__device__ float g_w2  [DD * DFF];      // transposed [1024][4096]
__device__ float g_bqkv[3 * DD];

// ---------------------------------------------------------------------------
// PTX helpers
// ---------------------------------------------------------------------------
__device__ __forceinline__ float round_tf32(float x) {
    uint32_t r;
    asm("cvt.rna.tf32.f32 %0, %1;" : "=r"(r) : "f"(x));
    return __uint_as_float(r);
}

__device__ __forceinline__ void mma_tf32(float c[4], const uint32_t a[4], const uint32_t b[2]) {
    asm volatile(
        "mma.sync.aligned.m16n8k8.row.col.f32.tf32.tf32.f32 "
        "{%0,%1,%2,%3}, {%4,%5,%6,%7}, {%8,%9}, {%0,%1,%2,%3};\n"
        : "+f"(c[0]), "+f"(c[1]), "+f"(c[2]), "+f"(c[3])
        : "r"(a[0]), "r"(a[1]), "r"(a[2]), "r"(a[3]), "r"(b[0]), "r"(b[1]));
}

__device__ __forceinline__ void ldsm_x4(uint32_t r[4], uint32_t addr) {
    asm volatile("ldmatrix.sync.aligned.m8n8.x4.shared.b16 {%0,%1,%2,%3}, [%4];"
                 : "=r"(r[0]), "=r"(r[1]), "=r"(r[2]), "=r"(r[3]) : "r"(addr));
}

__device__ __forceinline__ void cp_async16(float* smem_dst, const float* gmem_src) {
    uint32_t s = (uint32_t)__cvta_generic_to_shared(smem_dst);
    asm volatile("cp.async.cg.shared.global [%0], [%1], 16;\n" :: "r"(s), "l"(gmem_src));
}
__device__ __forceinline__ void cp_async_commit() {
    asm volatile("cp.async.commit_group;\n");
}
template<int N>
__device__ __forceinline__ void cp_async_wait() {
    asm volatile("cp.async.wait_group %0;\n" :: "n"(N));
}

__device__ __forceinline__ float gelu_exact(float x) {
    return 0.5f * x * (1.0f + erff(x * 0.70710678118654752f));
}

// ---------------------------------------------------------------------------
// Weight transpose prepass: dst[c][r] = round_tf32(src[r][c]).
// grid (C/32, R/32), block (32, 8).
// ---------------------------------------------------------------------------
__global__ void __launch_bounds__(256) transpose_kernel(
        const float* __restrict__ src, float* __restrict__ dst, int R, int C) {
    __shared__ float tile[32][33];
    const int r0 = blockIdx.y * 32, c0 = blockIdx.x * 32;
    const int tx = threadIdx.x, ty = threadIdx.y;
    #pragma unroll
    for (int i = 0; i < 32; i += 8)
        tile[ty + i][tx] = src[(size_t)(r0 + ty + i) * C + c0 + tx];
    __syncthreads();
    #pragma unroll
    for (int i = 0; i < 32; i += 8)
        dst[(size_t)(c0 + ty + i) * R + r0 + tx] = round_tf32(tile[tx][ty + i]);
}

__global__ void __launch_bounds__(256) bias_concat_kernel(
        const float* __restrict__ bq, const float* __restrict__ bk,
        const float* __restrict__ bv, float* __restrict__ bqkv) {
    int i = blockIdx.x * 256 + threadIdx.x;
    if (i < DD)            bqkv[i] = bq[i];
    else if (i < 2 * DD)   bqkv[i] = bk[i - DD];
    else if (i < 3 * DD)   bqkv[i] = bv[i - 2 * DD];
}

// ---------------------------------------------------------------------------
// LayerNorm: one block per row of 1024, 256 threads. Output tf32-rounded.
// ---------------------------------------------------------------------------
__device__ __forceinline__ float block_reduce_sum(float v, float* sh) {
    int lane = threadIdx.x & 31;
    int wid  = threadIdx.x >> 5;
    #pragma unroll
    for (int o = 16; o > 0; o >>= 1) v += __shfl_down_sync(0xffffffffu, v, o);
    if (lane == 0) sh[wid] = v;
    __syncthreads();
    if (wid == 0) {
        float t = (lane < 8) ? sh[lane] : 0.0f;
        #pragma unroll
        for (int o = 4; o > 0; o >>= 1) t += __shfl_down_sync(0xffffffffu, t, o);
        if (lane == 0) sh[0] = t;
    }
    __syncthreads();
    float r = sh[0];
    __syncthreads();
    return r;
}

__global__ void __launch_bounds__(256) ln_kernel(const float* __restrict__ x,
                                                 const float* __restrict__ g,
                                                 const float* __restrict__ b,
                                                 float* __restrict__ y) {
    __shared__ float sh[32];
    const int row = blockIdx.x;
    const float* xr = x + (size_t)row * DD;
    float v[4];
    float s = 0.0f;
    #pragma unroll
    for (int i = 0; i < 4; i++) { v[i] = xr[threadIdx.x + 256 * i]; s += v[i]; }
    s = block_reduce_sum(s, sh);
    const float mean = s * (1.0f / DD);
    float sq = 0.0f;
    #pragma unroll
    for (int i = 0; i < 4; i++) { float d = v[i] - mean; sq += d * d; }
    sq = block_reduce_sum(sq, sh);
    const float rstd = rsqrtf(sq * (1.0f / DD) + 1e-5f);
    float* yr = y + (size_t)row * DD;
    #pragma unroll
    for (int i = 0; i < 4; i++) {
        int c = threadIdx.x + 256 * i;
        yr[c] = round_tf32((v[i] - mean) * rstd * g[c] + b[c]);
    }
}

// ---------------------------------------------------------------------------
// TF32 tensor-core GEMM v5: C[M,N] = A[M,K] @ Bt[N,K]^T + bias (+ epilogue)
// BOTH operands K-major [rows][32k] stride 36 in smem; BOTH fragment loads
// via ldmatrix.x4 (A: verified R12 mapping; B: verified attention-K mapping).
// 128x128 CTA tile, 128 threads (4 warps, 2x2 of 64x64), 2-stage ring,
// 3 CTAs/SM. Mainloop per warp per K-tile: 32 LDSM + 128 MMA, zero LDS.
// EPI: 0 = none, 1 = exact GELU (tf32-rounded output), 2 = residual add
// ---------------------------------------------------------------------------
#define TS 36
#define T_FLOATS (128 * TS)                    // 4608
#define STG_FLOATS (2 * T_FLOATS)              // 9216
#define GEMM_SMEM_BYTES (2 * STG_FLOATS * 4)   // 73728

template<int EPI>
__global__ void __launch_bounds__(128, 3) gemm_tf32_kernel(
        const float* __restrict__ A, const float* __restrict__ Bt,
        const float* __restrict__ bias, const float* __restrict__ resid,
        float* __restrict__ C, int M, int N, int K) {
    extern __shared__ float smem[];
    const uint32_t smem_u32 = (uint32_t)__cvta_generic_to_shared(smem);

    const int bm = blockIdx.y * 128;
    const int bn = blockIdx.x * 128;
    const int tid  = threadIdx.x;
    const int warp = tid >> 5;
    const int lane = tid & 31;
    const int g    = lane >> 2;
    const int tig  = lane & 3;
    const int warp_m = (warp & 1) * 64;
    const int warp_n = (warp >> 1) * 64;

    // A fragments (R12-verified): tiles (r0-7,k0),(r8-15,k0),(r0-7,k+4),(r8-15,k+4)
    const uint32_t aoff = (uint32_t)((warp_m + (lane & 15)) * TS * 4)
                        + ((lane & 16) ? 16u : 0u);
    // B fragments (attention-K-verified): tiles (n0-7,k0),(n0-7,k+4),(n8-15,k0),(n8-15,k+4)
    const uint32_t boff = (uint32_t)((warp_n + (lane & 7)) * TS * 4)
                        + ((lane & 8) ? 16u : 0u)
                        + ((lane & 16) ? (uint32_t)(8 * TS * 4) : 0u);

    float acc[4][8][4];
    #pragma unroll
    for (int mf = 0; mf < 4; mf++)
        #pragma unroll
        for (int nf = 0; nf < 8; nf++)
            #pragma unroll
            for (int r = 0; r < 4; r++) acc[mf][nf][r] = 0.0f;

    const int NK = K >> 5;

    auto load_tile = [&](int kt) {
        float* As = smem + (kt & 1) * STG_FLOATS;
        float* Bs = As + T_FLOATS;
        const int k0 = kt << 5;
        #pragma unroll
        for (int i = 0; i < 8; i++) {
            int f = tid + 128 * i;
            int row = f >> 3, c4 = (f & 7) << 2;
            cp_async16(&As[row * TS + c4],
                       A + (size_t)(bm + row) * K + k0 + c4);
            cp_async16(&Bs[row * TS + c4],
                       Bt + (size_t)(bn + row) * K + k0 + c4);
        }
        cp_async_commit();
    };

    load_tile(0);
    load_tile(1);

    for (int kt = 0; kt < NK; kt++) {
        if (kt + 1 < NK) cp_async_wait<1>();
        else             cp_async_wait<0>();
        __syncthreads();

        const uint32_t As_u32 = smem_u32 + (kt & 1) * (STG_FLOATS * 4);
        const uint32_t Bs_u32 = As_u32 + T_FLOATS * 4;

        #pragma unroll
        for (int ks = 0; ks < 4; ks++) {
            uint32_t afrag[4][4];
            #pragma unroll
            for (int mf = 0; mf < 4; mf++)
                ldsm_x4(afrag[mf], As_u32 + aoff + mf * (16 * TS * 4) + ks * 32);
            #pragma unroll
            for (int np = 0; np < 4; np++) {
                uint32_t bb4[4];
                ldsm_x4(bb4, Bs_u32 + boff + np * (16 * TS * 4) + ks * 32);
                #pragma unroll
                for (int mf = 0; mf < 4; mf++) {
                    mma_tf32(acc[mf][2 * np    ], afrag[mf], bb4    );
                    mma_tf32(acc[mf][2 * np + 1], afrag[mf], bb4 + 2);
                }
            }
        }

        __syncthreads();
        if (kt + 2 < NK) load_tile(kt + 2);
    }

    #pragma unroll
    for (int mf = 0; mf < 4; mf++) {
        #pragma unroll
        for (int nf = 0; nf < 8; nf++) {
            const int row0 = bm + warp_m + mf * 16 + g;
            const int row1 = row0 + 8;
            const int col  = bn + warp_n + nf * 8 + 2 * tig;
            const float b0 = bias[col], b1 = bias[col + 1];
            float v0 = acc[mf][nf][0] + b0;
            float v1 = acc[mf][nf][1] + b1;
            float v2 = acc[mf][nf][2] + b0;
            float v3 = acc[mf][nf][3] + b1;
            if (EPI == 1) {
                v0 = round_tf32(gelu_exact(v0)); v1 = round_tf32(gelu_exact(v1));
                v2 = round_tf32(gelu_exact(v2)); v3 = round_tf32(gelu_exact(v3));
            }
            if (EPI == 2) {
                float2 r0v = *(const float2*)(resid + (size_t)row0 * N + col);
                float2 r1v = *(const float2*)(resid + (size_t)row1 * N + col);
                v0 += r0v.x; v1 += r0v.y; v2 += r1v.x; v3 += r1v.y;
            }
            *(float2*)(C + (size_t)row0 * N + col) = make_float2(v0, v1);
            *(float2*)(C + (size_t)row1 * N + col) = make_float2(v2, v3);
        }
    }
}

// ---------------------------------------------------------------------------
// Tensor-core masked flash attention v6 (byte-identical to R12).
// ---------------------------------------------------------------------------
#define QT 64
#define CH 64
#define O_QS  0                        // [64][68]
#define O_KS  4352                     // 2 x [64][68]
#define O_VS  13056                    // 2 x [64][72]
#define O_PS  22272                    // [64][68]
#define O_RED 26624                    // [64][2]
#define O_M   26752                    // [64]
#define O_L   26816                    // [64]
#define O_SC  26880                    // [64]
#define ATTN_SMEM_FLOATS 26944
#define ATTN_SMEM_BYTES (ATTN_SMEM_FLOATS * 4)   // 107776

__global__ void __launch_bounds__(256) attn_kernel(
        const float* __restrict__ QKV, float* __restrict__ O) {
    extern __shared__ float dyn[];
    float* Qs  = dyn + O_QS;
    float* Ks  = dyn + O_KS;
    float* Vs  = dyn + O_VS;
    float* Ps  = dyn + O_PS;
    float* red = dyn + O_RED;
    float* mS  = dyn + O_M;
    float* lS  = dyn + O_L;
    float* scS = dyn + O_SC;
    const uint32_t dyn_u32 = (uint32_t)__cvta_generic_to_shared(dyn);

    const int qbase = blockIdx.x * QT;
    const int h  = blockIdx.y;
    const int b  = blockIdx.z;
    const int tid = threadIdx.x;
    const int warp = tid >> 5, lane = tid & 31;
    const int g = lane >> 2, tig = lane & 3;
    const int m0 = (warp >> 1) * 16;
    const int n0 = (warp & 1) * 32;
    const int w2 = warp & 1;
    const int pairbar = (warp >> 1) + 1;

    #define PAIR_BAR() asm volatile("bar.sync %0, 64;" :: "r"(pairbar) : "memory")

    const int RS = 3 * DD;
    const uint32_t qoff = (uint32_t)((m0 + (lane & 15)) * 68 * 4)
                        + ((lane & 16) ? 16u : 0u);
    const uint32_t koff = (uint32_t)((n0 + (lane & 7)) * 68 * 4)
                        + ((lane & 8) ? 16u : 0u)
                        + ((lane & 16) ? (uint32_t)(8 * 68 * 4) : 0u);
    const uint32_t Ps_u32 = dyn_u32 + O_PS * 4;

    int clo = max(0, (qbase - WINDOW) >> 6);
    int chi = min(SS / CH - 1, (qbase + QT - 1 + WINDOW) >> 6);
    if (qbase < NGLOBAL) { clo = 0; chi = SS / CH - 1; }

    auto load_kv = [&](int cc, int bf) {
        const int r = tid >> 4, d4 = tid & 15;
        float* Kb = Ks + bf * 4352;
        float* Vb = Vs + bf * 4608;
        #pragma unroll
        for (int it = 0; it < 4; it++) {
            int rr = r + it * 16;
            const float* src = QKV + (size_t)(b * SS + CH * cc + rr) * RS + h * DKK + d4 * 4;
            cp_async16(Kb + rr * 68 + d4 * 4, src + DD);
            cp_async16(Vb + rr * 72 + d4 * 4, src + 2 * DD);
        }
        cp_async_commit();
    };

    {
        const int r = tid >> 4, d4 = tid & 15;
        #pragma unroll
        for (int it = 0; it < 4; it++) {
            int qi = r + it * 16;
            cp_async16(Qs + qi * 68 + d4 * 4,
                       QKV + (size_t)(b * SS + qbase + qi) * RS + h * DKK + d4 * 4);
        }
        cp_async_commit();
    }
    load_kv(0, 0);

    if (tid < QT) { mS[tid] = -INFINITY; lS[tid] = 0.0f; }

    float o_acc[4][4];
    #pragma unroll
    for (int nf = 0; nf < 4; nf++)
        #pragma unroll
        for (int r = 0; r < 4; r++) o_acc[nf][r] = 0.0f;

    const int i0 = qbase + m0 + g;
    const int i1 = i0 + 8;
    const bool gi0 = (i0 < NGLOBAL);
    const bool gi1 = (i1 < NGLOBAL);

    int c = 0, buf = 0;
    while (c >= 0) {
        int nc;
        if (c == 0) nc = (clo > 0) ? clo : (chi >= 1 ? 1 : -1);
        else        nc = (c + 1 <= chi) ? c + 1 : -1;

        if (nc >= 0) {
            load_kv(nc, buf ^ 1);
            cp_async_wait<1>();
        } else {
            cp_async_wait<0>();
        }
        __syncthreads();

        const uint32_t Kb_u32 = dyn_u32 + (O_KS + buf * 4352) * 4;
        const float* Vb = Vs + buf * 4608;

        float s[4][4];
        #pragma unroll
        for (int nf = 0; nf < 4; nf++)
            #pragma unroll
            for (int r = 0; r < 4; r++) s[nf][r] = 0.0f;
        #pragma unroll
        for (int ks = 0; ks < 8; ks++) {
            uint32_t a[4];
            ldsm_x4(a, dyn_u32 + qoff + ks * 32);
            #pragma unroll
            for (int np = 0; np < 2; np++) {
                uint32_t bb4[4];
                ldsm_x4(bb4, Kb_u32 + koff + np * (16 * 68 * 4) + ks * 32);
                mma_tf32(s[2 * np    ], a, bb4    );
                mma_tf32(s[2 * np + 1], a, bb4 + 2);
            }
        }

        float mx0 = -INFINITY, mx1 = -INFINITY;
        #pragma unroll
        for (int nf = 0; nf < 4; nf++) {
            const int j0 = CH * c + n0 + nf * 8 + 2 * tig;
            const int j1 = j0 + 1;
            const bool vj0 = (j0 < NGLOBAL), vj1 = (j1 < NGLOBAL);
            s[nf][0] = (gi0 || vj0 || abs(i0 - j0) <= WINDOW) ? s[nf][0] * 0.125f : -INFINITY;
            s[nf][1] = (gi0 || vj1 || abs(i0 - j1) <= WINDOW) ? s[nf][1] * 0.125f : -INFINITY;
            s[nf][2] = (gi1 || vj0 || abs(i1 - j0) <= WINDOW) ? s[nf][2] * 0.125f : -INFINITY;
            s[nf][3] = (gi1 || vj1 || abs(i1 - j1) <= WINDOW) ? s[nf][3] * 0.125f : -INFINITY;
            mx0 = fmaxf(mx0, fmaxf(s[nf][0], s[nf][1]));
            mx1 = fmaxf(mx1, fmaxf(s[nf][2], s[nf][3]));
        }
        mx0 = fmaxf(mx0, __shfl_xor_sync(0xffffffffu, mx0, 1));
        mx0 = fmaxf(mx0, __shfl_xor_sync(0xffffffffu, mx0, 2));
        mx1 = fmaxf(mx1, __shfl_xor_sync(0xffffffffu, mx1, 1));
        mx1 = fmaxf(mx1, __shfl_xor_sync(0xffffffffu, mx1, 2));
        if (tig == 0) {
            red[(m0 + g    ) * 2 + w2] = mx0;
            red[(m0 + g + 8) * 2 + w2] = mx1;
        }
        PAIR_BAR();

        if (w2 == 0 && tig == 0) {
            const int r0 = m0 + g, r1 = m0 + g + 8;
            float mn0 = fmaxf(fmaxf(red[r0 * 2], red[r0 * 2 + 1]), mS[r0]);
            scS[r0] = __expf(mS[r0] - mn0);
            mS[r0]  = mn0;
            float mn1 = fmaxf(fmaxf(red[r1 * 2], red[r1 * 2 + 1]), mS[r1]);
            scS[r1] = __expf(mS[r1] - mn1);
            mS[r1]  = mn1;
        }
        PAIR_BAR();

        const float m0v = mS[m0 + g], m1v = mS[m0 + g + 8];
        float sum0 = 0.0f, sum1 = 0.0f;
        #pragma unroll
        for (int nf = 0; nf < 4; nf++) {
            s[nf][0] = __expf(s[nf][0] - m0v);
            s[nf][1] = __expf(s[nf][1] - m0v);
            s[nf][2] = __expf(s[nf][2] - m1v);
            s[nf][3] = __expf(s[nf][3] - m1v);
            sum0 += s[nf][0] + s[nf][1];
            sum1 += s[nf][2] + s[nf][3];
            const int col = n0 + nf * 8 + 2 * tig;
            *(float2*)&Ps[(m0 + g    ) * 68 + col] = make_float2(s[nf][0], s[nf][1]);
            *(float2*)&Ps[(m0 + g + 8) * 68 + col] = make_float2(s[nf][2], s[nf][3]);
        }
        sum0 += __shfl_xor_sync(0xffffffffu, sum0, 1);
        sum0 += __shfl_xor_sync(0xffffffffu, sum0, 2);
        sum1 += __shfl_xor_sync(0xffffffffu, sum1, 1);
        sum1 += __shfl_xor_sync(0xffffffffu, sum1, 2);
        if (tig == 0) {
            red[(m0 + g    ) * 2 + w2] = sum0;
            red[(m0 + g + 8) * 2 + w2] = sum1;
        }
        {
            const float sc0 = scS[m0 + g], sc1 = scS[m0 + g + 8];
            #pragma unroll
            for (int nf = 0; nf < 4; nf++) {
                o_acc[nf][0] *= sc0; o_acc[nf][1] *= sc0;
                o_acc[nf][2] *= sc1; o_acc[nf][3] *= sc1;
            }
        }
        PAIR_BAR();

        if (w2 == 0 && tig == 0) {
            const int r0 = m0 + g, r1 = m0 + g + 8;
            lS[r0] = lS[r0] * scS[r0] + red[r0 * 2] + red[r0 * 2 + 1];
            lS[r1] = lS[r1] * scS[r1] + red[r1 * 2] + red[r1 * 2 + 1];
        }

        #pragma unroll
        for (int ks = 0; ks < 8; ks++) {
            const int kk = ks << 3;
            uint32_t a[4];
            ldsm_x4(a, Ps_u32 + qoff + ks * 32);
            #pragma unroll
            for (int nf = 0; nf < 4; nf++) {
                uint32_t bb[2];
                bb[0] = __float_as_uint(Vb[(kk + tig    ) * 72 + n0 + nf * 8 + g]);
                bb[1] = __float_as_uint(Vb[(kk + tig + 4) * 72 + n0 + nf * 8 + g]);
                mma_tf32(o_acc[nf], a, bb);
            }
        }

        __syncthreads();

        c = nc;
        buf ^= 1;
    }

    const float inv0 = 1.0f / lS[m0 + g];
    const float inv1 = 1.0f / lS[m0 + g + 8];
    #pragma unroll
    for (int nf = 0; nf < 4; nf++) {
        const int col = h * DKK + n0 + nf * 8 + 2 * tig;
        float* o0 = O + (size_t)(b * SS + qbase + m0 + g    ) * DD + col;
        float* o1 = O + (size_t)(b * SS + qbase + m0 + g + 8) * DD + col;
        *(float2*)o0 = make_float2(o_acc[nf][0] * inv0, o_acc[nf][1] * inv0);
        *(float2*)o1 = make_float2(o_acc[nf][2] * inv1, o_acc[nf][3] * inv1);
    }
    #undef PAIR_BAR
}

// ---------------------------------------------------------------------------
// Launch
// ---------------------------------------------------------------------------
extern "C" void kernel_launch(void* const* d_in, const int* in_sizes, int n_in,
                              void* d_out, int out_size) {
    const float* x     = (const float*)d_in[0];
    const float* Wq    = (const float*)d_in[1];
    const float* bq    = (const float*)d_in[2];
    const float* Wk    = (const float*)d_in[3];
    const float* bk    = (const float*)d_in[4];
    const float* Wv    = (const float*)d_in[5];
    const float* bv    = (const float*)d_in[6];
    const float* Wo    = (const float*)d_in[7];
    const float* bo    = (const float*)d_in[8];
    const float* ln1_g = (const float*)d_in[9];
    const float* ln1_b = (const float*)d_in[10];
    const float* W1    = (const float*)d_in[11];
    const float* b1    = (const float*)d_in[12];
    const float* W2    = (const float*)d_in[13];
    const float* b2    = (const float*)d_in[14];
    const float* ln2_g = (const float*)d_in[15];
    const float* ln2_b = (const float*)d_in[16];
    float* out = (float*)d_out;

    float *xn, *qkv, *att, *x1, *xn2, *hbuf, *wqkv, *wo, *w1, *w2, *bqkv;
    cudaGetSymbolAddress((void**)&xn,   g_xn);
    cudaGetSymbolAddress((void**)&qkv,  g_qkv);
    cudaGetSymbolAddress((void**)&att,  g_att);
    cudaGetSymbolAddress((void**)&x1,   g_x1);
    cudaGetSymbolAddress((void**)&xn2,  g_xn2);
    cudaGetSymbolAddress((void**)&hbuf, g_h);
    cudaGetSymbolAddress((void**)&wqkv, g_wqkv);
    cudaGetSymbolAddress((void**)&wo,   g_wo);
    cudaGetSymbolAddress((void**)&w1,   g_w1);
    cudaGetSymbolAddress((void**)&w2,   g_w2);
    cudaGetSymbolAddress((void**)&bqkv, g_bqkv);

    cudaFuncSetAttribute(gemm_tf32_kernel<0>,
        cudaFuncAttributeMaxDynamicSharedMemorySize, GEMM_SMEM_BYTES);
    cudaFuncSetAttribute(gemm_tf32_kernel<1>,
        cudaFuncAttributeMaxDynamicSharedMemorySize, GEMM_SMEM_BYTES);
    cudaFuncSetAttribute(gemm_tf32_kernel<2>,
        cudaFuncAttributeMaxDynamicSharedMemorySize, GEMM_SMEM_BYTES);
    cudaFuncSetAttribute(attn_kernel,
        cudaFuncAttributeMaxDynamicSharedMemorySize, ATTN_SMEM_BYTES);

    // 0) prepass: transpose + tf32-round all weights ([N][K] layout), concat biases
    dim3 tb(32, 8);
    transpose_kernel<<<dim3(32, 32), tb>>>(Wq, wqkv,                  1024, 1024);
    transpose_kernel<<<dim3(32, 32), tb>>>(Wk, wqkv + 1024 * 1024,    1024, 1024);
    transpose_kernel<<<dim3(32, 32), tb>>>(Wv, wqkv + 2 * 1024 * 1024, 1024, 1024);
    transpose_kernel<<<dim3(32, 32), tb>>>(Wo, wo, 1024, 1024);
    transpose_kernel<<<dim3(DFF / 32, DD / 32), tb>>>(W1, w1, DD, DFF);
    transpose_kernel<<<dim3(DD / 32, DFF / 32), tb>>>(W2, w2, DFF, DD);
    bias_concat_kernel<<<12, 256>>>(bq, bk, bv, bqkv);

    // 1) xn = LN(x)
    ln_kernel<<<MM, 256>>>(x, ln1_g, ln1_b, xn);

    // 2) qkv = xn @ Wqkv + bqkv
    dim3 gq(3 * DD / 128, MM / 128);
    gemm_tf32_kernel<0><<<gq, 128, GEMM_SMEM_BYTES>>>(xn, wqkv, bqkv, nullptr,
                                                      qkv, MM, 3 * DD, DD);

    // 3) tensor-core masked attention
    attn_kernel<<<dim3(SS / QT, HH, BB), 256, ATTN_SMEM_BYTES>>>(qkv, att);

    // 4) x1 = x + att @ Wo + bo
    dim3 g1(DD / 128, MM / 128);
    gemm_tf32_kernel<2><<<g1, 128, GEMM_SMEM_BYTES>>>(att, wo, bo, x, x1, MM, DD, DD);

    // 5) xn2 = LN(x1)
    ln_kernel<<<MM, 256>>>(x1, ln2_g, ln2_b, xn2);

    // 6) h = gelu(xn2 @ W1 + b1)
    dim3 g2(DFF / 128, MM / 128);
    gemm_tf32_kernel<1><<<g2, 128, GEMM_SMEM_BYTES>>>(xn2, w1, b1, nullptr, hbuf, MM, DFF, DD);

    // 7) out = x1 + h @ W2 + b2
    gemm_tf32_kernel<2><<<g1, 128, GEMM_SMEM_BYTES>>>(hbuf, w2, b2, x1, out, MM, DD, DFF);
}

// round 14
// speedup vs baseline: 1.0189x; 1.0189x over previous
#include <cuda_runtime.h>
#include <math.h>
#include <stdint.h>

// ---------------------------------------------------------------------------
// Problem constants
// ---------------------------------------------------------------------------
#define BB 2
#define SS 2048
#define DD 1024
#define HH 16
#define DKK 64
#define DFF 4096
#define WINDOW 128
#define NGLOBAL 16
#define MM (BB * SS)   // 4096 rows

// ---------------------------------------------------------------------------
// Scratch (device globals; no allocation allowed)
// ---------------------------------------------------------------------------
__device__ float g_xn  [MM * DD];
__device__ float g_qkv [MM * 3 * DD];
__device__ float g_att [MM * DD];
__device__ float g_x1  [MM * DD];
__device__ float g_xn2 [MM * DD];
__device__ float g_h   [MM * DFF];
__device__ float g_wqkv[DD * 3 * DD];
__device__ float g_wo  [DD * DD];
__device__ float g_w1  [DD * DFF];
__device__ float g_w2  [DFF * DD];
__device__ float g_bqkv[3 * DD];

// ---------------------------------------------------------------------------
// PTX helpers
// ---------------------------------------------------------------------------
__device__ __forceinline__ float round_tf32(float x) {
    uint32_t r;
    asm("cvt.rna.tf32.f32 %0, %1;" : "=r"(r) : "f"(x));
    return __uint_as_float(r);
}
__device__ __forceinline__ float4 rtf4(float4 v) {
    v.x = round_tf32(v.x); v.y = round_tf32(v.y);
    v.z = round_tf32(v.z); v.w = round_tf32(v.w);
    return v;
}

__device__ __forceinline__ void mma_tf32(float c[4], const uint32_t a[4], const uint32_t b[2]) {
    asm volatile(
        "mma.sync.aligned.m16n8k8.row.col.f32.tf32.tf32.f32 "
        "{%0,%1,%2,%3}, {%4,%5,%6,%7}, {%8,%9}, {%0,%1,%2,%3};\n"
        : "+f"(c[0]), "+f"(c[1]), "+f"(c[2]), "+f"(c[3])
        : "r"(a[0]), "r"(a[1]), "r"(a[2]), "r"(a[3]), "r"(b[0]), "r"(b[1]));
}

__device__ __forceinline__ void ldsm_x4(uint32_t r[4], uint32_t addr) {
    asm volatile("ldmatrix.sync.aligned.m8n8.x4.shared.b16 {%0,%1,%2,%3}, [%4];"
                 : "=r"(r[0]), "=r"(r[1]), "=r"(r[2]), "=r"(r[3]) : "r"(addr));
}

__device__ __forceinline__ void cp_async16(float* smem_dst, const float* gmem_src) {
    uint32_t s = (uint32_t)__cvta_generic_to_shared(smem_dst);
    asm volatile("cp.async.cg.shared.global [%0], [%1], 16;\n" :: "r"(s), "l"(gmem_src));
}
__device__ __forceinline__ void cp_async_commit() {
    asm volatile("cp.async.commit_group;\n");
}
template<int N>
__device__ __forceinline__ void cp_async_wait() {
    asm volatile("cp.async.wait_group %0;\n" :: "n"(N));
}

__device__ __forceinline__ float gelu_exact(float x) {
    return 0.5f * x * (1.0f + erff(x * 0.70710678118654752f));
}

// ---------------------------------------------------------------------------
// Fused prepass (R12): round weights to tf32, concat QKV weights + biases.
// One launch.
// ---------------------------------------------------------------------------
#define PREP_TOTAL 3146496
__global__ void __launch_bounds__(256) prep_kernel(
        const float4* __restrict__ Wq, const float4* __restrict__ Wk,
        const float4* __restrict__ Wv, const float4* __restrict__ Wo,
        const float4* __restrict__ W1, const float4* __restrict__ W2,
        const float4* __restrict__ bq, const float4* __restrict__ bk,
        const float4* __restrict__ bv,
        float4* __restrict__ wqkv, float4* __restrict__ wo,
        float4* __restrict__ w1, float4* __restrict__ w2,
        float4* __restrict__ bqkv) {
    int idx = blockIdx.x * 256 + threadIdx.x;
    if (idx < 786432) {
        int sub = idx >> 18;            // 0..2
        int k   = idx & 262143;
        int r   = k >> 8, c = k & 255;
        const float4* src = (sub == 0) ? Wq : (sub == 1) ? Wk : Wv;
        wqkv[r * 768 + sub * 256 + c] = rtf4(src[k]);
    } else if (idx < 1048576) {
        int k = idx - 786432;
        wo[k] = rtf4(Wo[k]);
    } else if (idx < 2097152) {
        int k = idx - 1048576;
        w1[k] = rtf4(W1[k]);
    } else if (idx < 3145728) {
        int k = idx - 2097152;
        w2[k] = rtf4(W2[k]);
    } else if (idx < PREP_TOTAL) {
        int k = idx - 3145728;          // 0..767
        int sub = k >> 8, c = k & 255;
        const float4* src = (sub == 0) ? bq : (sub == 1) ? bk : bv;
        bqkv[sub * 256 + c] = src[c];
    }
}

// ---------------------------------------------------------------------------
// LayerNorm: one block per row of 1024, 256 threads. Output tf32-rounded.
// ---------------------------------------------------------------------------
__device__ __forceinline__ float block_reduce_sum(float v, float* sh) {
    int lane = threadIdx.x & 31;
    int wid  = threadIdx.x >> 5;
    #pragma unroll
    for (int o = 16; o > 0; o >>= 1) v += __shfl_down_sync(0xffffffffu, v, o);
    if (lane == 0) sh[wid] = v;
    __syncthreads();
    if (wid == 0) {
        float t = (lane < 8) ? sh[lane] : 0.0f;
        #pragma unroll
        for (int o = 4; o > 0; o >>= 1) t += __shfl_down_sync(0xffffffffu, t, o);
        if (lane == 0) sh[0] = t;
    }
    __syncthreads();
    float r = sh[0];
    __syncthreads();
    return r;
}

__global__ void __launch_bounds__(256) ln_kernel(const float* __restrict__ x,
                                                 const float* __restrict__ g,
                                                 const float* __restrict__ b,
                                                 float* __restrict__ y) {
    __shared__ float sh[32];
    const int row = blockIdx.x;
    const float* xr = x + (size_t)row * DD;
    float v[4];
    float s = 0.0f;
    #pragma unroll
    for (int i = 0; i < 4; i++) { v[i] = xr[threadIdx.x + 256 * i]; s += v[i]; }
    s = block_reduce_sum(s, sh);
    const float mean = s * (1.0f / DD);
    float sq = 0.0f;
    #pragma unroll
    for (int i = 0; i < 4; i++) { float d = v[i] - mean; sq += d * d; }
    sq = block_reduce_sum(sq, sh);
    const float rstd = rsqrtf(sq * (1.0f / DD) + 1e-5f);
    float* yr = y + (size_t)row * DD;
    #pragma unroll
    for (int i = 0; i < 4; i++) {
        int c = threadIdx.x + 256 * i;
        yr[c] = round_tf32((v[i] - mean) * rstd * g[c] + b[c]);
    }
}

// ---------------------------------------------------------------------------
// TF32 tensor-core GEMM v4 (R12, best so far): A fragments via ldmatrix.x4,
// B via scalar LDS. 128x128 CTA tile, 128 threads (4 warps, 2x2 of 64x64),
// 2-stage ring, 3 CTAs/SM.
// ---------------------------------------------------------------------------
#define AS_STRIDE 36
#define BS_STRIDE 136
#define AS_FLOATS (128 * AS_STRIDE)
#define BS_FLOATS (32 * BS_STRIDE)
#define STG_FLOATS (AS_FLOATS + BS_FLOATS)     // 8960
#define GEMM_SMEM_BYTES (2 * STG_FLOATS * 4)   // 71680

template<int EPI>
__global__ void __launch_bounds__(128, 3) gemm_tf32_kernel(
        const float* __restrict__ A, const float* __restrict__ B,
        const float* __restrict__ bias, const float* __restrict__ resid,
        float* __restrict__ C, int M, int N, int K) {
    extern __shared__ float smem[];
    const uint32_t smem_u32 = (uint32_t)__cvta_generic_to_shared(smem);

    const int bm = blockIdx.y * 128;
    const int bn = blockIdx.x * 128;
    const int tid  = threadIdx.x;
    const int warp = tid >> 5;
    const int lane = tid & 31;
    const int g    = lane >> 2;
    const int tig  = lane & 3;
    const int warp_m = (warp & 1) * 64;
    const int warp_n = (warp >> 1) * 64;

    const uint32_t aoff = (uint32_t)((warp_m + (lane & 15)) * AS_STRIDE * 4)
                        + ((lane & 16) ? 16u : 0u);

    float acc[4][8][4];
    #pragma unroll
    for (int mf = 0; mf < 4; mf++)
        #pragma unroll
        for (int nf = 0; nf < 8; nf++)
            #pragma unroll
            for (int r = 0; r < 4; r++) acc[mf][nf][r] = 0.0f;

    const int NK = K >> 5;

    auto load_tile = [&](int kt) {
        float* As = smem + (kt & 1) * STG_FLOATS;
        float* Bs = As + AS_FLOATS;
        const int k0 = kt << 5;
        #pragma unroll
        for (int i = 0; i < 8; i++) {
            int f = tid + 128 * i;
            int row = f >> 3, c4 = (f & 7) << 2;
            cp_async16(&As[row * AS_STRIDE + c4],
                       A + (size_t)(bm + row) * K + k0 + c4);
        }
        #pragma unroll
        for (int i = 0; i < 8; i++) {
            int f = tid + 128 * i;
            int row = f >> 5, c4 = (f & 31) << 2;
            cp_async16(&Bs[row * BS_STRIDE + c4],
                       B + (size_t)(k0 + row) * N + bn + c4);
        }
        cp_async_commit();
    };

    load_tile(0);
    load_tile(1);

    for (int kt = 0; kt < NK; kt++) {
        if (kt + 1 < NK) cp_async_wait<1>();
        else             cp_async_wait<0>();
        __syncthreads();

        const uint32_t As_u32 = smem_u32 + (kt & 1) * (STG_FLOATS * 4);
        const float* Bs = smem + (kt & 1) * STG_FLOATS + AS_FLOATS;

        #pragma unroll
        for (int ks = 0; ks < 4; ks++) {
            const int kk = ks << 3;
            uint32_t afrag[4][4];
            #pragma unroll
            for (int mf = 0; mf < 4; mf++)
                ldsm_x4(afrag[mf], As_u32 + aoff + mf * (16 * AS_STRIDE * 4) + ks * 32);
            #pragma unroll
            for (int half = 0; half < 2; half++) {
                uint32_t bfrag[4][2];
                #pragma unroll
                for (int nf = 0; nf < 4; nf++) {
                    const int c0 = warp_n + (half * 4 + nf) * 8 + g;
                    bfrag[nf][0] = __float_as_uint(Bs[(kk + tig    ) * BS_STRIDE + c0]);
                    bfrag[nf][1] = __float_as_uint(Bs[(kk + tig + 4) * BS_STRIDE + c0]);
                }
                #pragma unroll
                for (int mf = 0; mf < 4; mf++)
                    #pragma unroll
                    for (int nf = 0; nf < 4; nf++)
                        mma_tf32(acc[mf][half * 4 + nf], afrag[mf], bfrag[nf]);
            }
        }

        __syncthreads();
        if (kt + 2 < NK) load_tile(kt + 2);
    }

    #pragma unroll
    for (int mf = 0; mf < 4; mf++) {
        #pragma unroll
        for (int nf = 0; nf < 8; nf++) {
            const int row0 = bm + warp_m + mf * 16 + g;
            const int row1 = row0 + 8;
            const int col  = bn + warp_n + nf * 8 + 2 * tig;
            const float b0 = bias[col], b1 = bias[col + 1];
            float v0 = acc[mf][nf][0] + b0;
            float v1 = acc[mf][nf][1] + b1;
            float v2 = acc[mf][nf][2] + b0;
            float v3 = acc[mf][nf][3] + b1;
            if (EPI == 1) {
                v0 = round_tf32(gelu_exact(v0)); v1 = round_tf32(gelu_exact(v1));
                v2 = round_tf32(gelu_exact(v2)); v3 = round_tf32(gelu_exact(v3));
            }
            if (EPI == 2) {
                float2 r0v = *(const float2*)(resid + (size_t)row0 * N + col);
                float2 r1v = *(const float2*)(resid + (size_t)row1 * N + col);
                v0 += r0v.x; v1 += r0v.y; v2 += r1v.x; v3 += r1v.y;
            }
            *(float2*)(C + (size_t)row0 * N + col) = make_float2(v0, v1);
            *(float2*)(C + (size_t)row1 * N + col) = make_float2(v2, v3);
        }
    }
}

// ---------------------------------------------------------------------------
// Tensor-core masked flash attention v7: warp-local softmax.
// 64 q/block, 128 threads (4 warps). Each warp owns 16 query rows x all 64
// key cols. Row m/l/sc state lives in REGISTERS (replicated over the 4-lane
// group, reduced by shfl) — zero softmax barriers, zero softmax smem.
// Only the P C->A layout round-trip stays in smem, guarded by __syncwarp.
// Double-buffered K/V prefetch as before; 2 block syncs per chunk total.
// ---------------------------------------------------------------------------
#define QT 64
#define CH 64
#define O_QS  0                        // [64][68]
#define O_KS  4352                     // 2 x [64][68]
#define O_VS  13056                    // 2 x [64][72]
#define O_PS  22272                    // [64][68]
#define ATTN_SMEM_FLOATS 26624
#define ATTN_SMEM_BYTES (ATTN_SMEM_FLOATS * 4)   // 106496

__global__ void __launch_bounds__(128) attn_kernel(
        const float* __restrict__ QKV, float* __restrict__ O) {
    extern __shared__ float dyn[];
    float* Qs  = dyn + O_QS;
    float* Ks  = dyn + O_KS;
    float* Vs  = dyn + O_VS;
    float* Ps  = dyn + O_PS;
    const uint32_t dyn_u32 = (uint32_t)__cvta_generic_to_shared(dyn);

    const int qbase = blockIdx.x * QT;
    const int h  = blockIdx.y;
    const int b  = blockIdx.z;
    const int tid = threadIdx.x;
    const int warp = tid >> 5, lane = tid & 31;
    const int g = lane >> 2, tig = lane & 3;
    const int m0 = warp * 16;            // warp owns rows m0..m0+15, all 64 cols
    const int RS = 3 * DD;

    const uint32_t qoff = (uint32_t)((m0 + (lane & 15)) * 68 * 4)
                        + ((lane & 16) ? 16u : 0u);
    const uint32_t koff = (uint32_t)((lane & 7) * 68 * 4)
                        + ((lane & 8) ? 16u : 0u)
                        + ((lane & 16) ? (uint32_t)(8 * 68 * 4) : 0u);
    const uint32_t Ps_u32 = dyn_u32 + O_PS * 4;

    int clo = max(0, (qbase - WINDOW) >> 6);
    int chi = min(SS / CH - 1, (qbase + QT - 1 + WINDOW) >> 6);
    if (qbase < NGLOBAL) { clo = 0; chi = SS / CH - 1; }

    auto load_kv = [&](int cc, int bf) {
        const int r = tid >> 4, d4 = tid & 15;   // 8 rows x 16 d4 per pass
        float* Kb = Ks + bf * 4352;
        float* Vb = Vs + bf * 4608;
        #pragma unroll
        for (int it = 0; it < 8; it++) {
            int rr = r + it * 8;
            const float* src = QKV + (size_t)(b * SS + CH * cc + rr) * RS + h * DKK + d4 * 4;
            cp_async16(Kb + rr * 68 + d4 * 4, src + DD);
            cp_async16(Vb + rr * 72 + d4 * 4, src + 2 * DD);
        }
        cp_async_commit();
    };

    {
        const int r = tid >> 4, d4 = tid & 15;
        #pragma unroll
        for (int it = 0; it < 8; it++) {
            int qi = r + it * 8;
            cp_async16(Qs + qi * 68 + d4 * 4,
                       QKV + (size_t)(b * SS + qbase + qi) * RS + h * DKK + d4 * 4);
        }
        cp_async_commit();
    }
    load_kv(0, 0);

    // per-lane register softmax state for rows m0+g and m0+g+8
    float mrow0 = -INFINITY, mrow1 = -INFINITY;
    float lrow0 = 0.0f, lrow1 = 0.0f;

    float o_acc[8][4];
    #pragma unroll
    for (int nf = 0; nf < 8; nf++)
        #pragma unroll
        for (int r = 0; r < 4; r++) o_acc[nf][r] = 0.0f;

    const int i0 = qbase + m0 + g;
    const int i1 = i0 + 8;
    const bool gi0 = (i0 < NGLOBAL);
    const bool gi1 = (i1 < NGLOBAL);

    int c = 0, buf = 0;
    while (c >= 0) {
        int nc;
        if (c == 0) nc = (clo > 0) ? clo : (chi >= 1 ? 1 : -1);
        else        nc = (c + 1 <= chi) ? c + 1 : -1;

        if (nc >= 0) {
            load_kv(nc, buf ^ 1);
            cp_async_wait<1>();
        } else {
            cp_async_wait<0>();
        }
        __syncthreads();   // K/V of chunk c visible

        const uint32_t Kb_u32 = dyn_u32 + (O_KS + buf * 4352) * 4;
        const float* Vb = Vs + buf * 4608;

        // ---- S = Q @ K^T : 16x64 per warp ----
        float s[8][4];
        #pragma unroll
        for (int nf = 0; nf < 8; nf++)
            #pragma unroll
            for (int r = 0; r < 4; r++) s[nf][r] = 0.0f;
        #pragma unroll
        for (int ks = 0; ks < 8; ks++) {
            uint32_t a[4];
            ldsm_x4(a, dyn_u32 + qoff + ks * 32);
            #pragma unroll
            for (int np = 0; np < 4; np++) {
                uint32_t bb4[4];
                ldsm_x4(bb4, Kb_u32 + koff + np * (16 * 68 * 4) + ks * 32);
                mma_tf32(s[2 * np    ], a, bb4    );
                mma_tf32(s[2 * np + 1], a, bb4 + 2);
            }
        }

        // ---- mask + scale, warp-local row max ----
        float mx0 = -INFINITY, mx1 = -INFINITY;
        #pragma unroll
        for (int nf = 0; nf < 8; nf++) {
            const int j0 = CH * c + nf * 8 + 2 * tig;
            const int j1 = j0 + 1;
            const bool vj0 = (j0 < NGLOBAL), vj1 = (j1 < NGLOBAL);
            s[nf][0] = (gi0 || vj0 || abs(i0 - j0) <= WINDOW) ? s[nf][0] * 0.125f : -INFINITY;
            s[nf][1] = (gi0 || vj1 || abs(i0 - j1) <= WINDOW) ? s[nf][1] * 0.125f : -INFINITY;
            s[nf][2] = (gi1 || vj0 || abs(i1 - j0) <= WINDOW) ? s[nf][2] * 0.125f : -INFINITY;
            s[nf][3] = (gi1 || vj1 || abs(i1 - j1) <= WINDOW) ? s[nf][3] * 0.125f : -INFINITY;
            mx0 = fmaxf(mx0, fmaxf(s[nf][0], s[nf][1]));
            mx1 = fmaxf(mx1, fmaxf(s[nf][2], s[nf][3]));
        }
        mx0 = fmaxf(mx0, __shfl_xor_sync(0xffffffffu, mx0, 1));
        mx0 = fmaxf(mx0, __shfl_xor_sync(0xffffffffu, mx0, 2));
        mx1 = fmaxf(mx1, __shfl_xor_sync(0xffffffffu, mx1, 1));
        mx1 = fmaxf(mx1, __shfl_xor_sync(0xffffffffu, mx1, 2));

        // register m/sc update (no smem, no barrier)
        const float mn0 = fmaxf(mrow0, mx0);
        const float mn1 = fmaxf(mrow1, mx1);
        const float sc0 = __expf(mrow0 - mn0);
        const float sc1 = __expf(mrow1 - mn1);
        mrow0 = mn0; mrow1 = mn1;

        // ---- exp + sums + store P ----
        float sum0 = 0.0f, sum1 = 0.0f;
        #pragma unroll
        for (int nf = 0; nf < 8; nf++) {
            s[nf][0] = __expf(s[nf][0] - mn0);
            s[nf][1] = __expf(s[nf][1] - mn0);
            s[nf][2] = __expf(s[nf][2] - mn1);
            s[nf][3] = __expf(s[nf][3] - mn1);
            sum0 += s[nf][0] + s[nf][1];
            sum1 += s[nf][2] + s[nf][3];
            const int col = nf * 8 + 2 * tig;
            *(float2*)&Ps[(m0 + g    ) * 68 + col] = make_float2(s[nf][0], s[nf][1]);
            *(float2*)&Ps[(m0 + g + 8) * 68 + col] = make_float2(s[nf][2], s[nf][3]);
        }
        sum0 += __shfl_xor_sync(0xffffffffu, sum0, 1);
        sum0 += __shfl_xor_sync(0xffffffffu, sum0, 2);
        sum1 += __shfl_xor_sync(0xffffffffu, sum1, 1);
        sum1 += __shfl_xor_sync(0xffffffffu, sum1, 2);
        lrow0 = lrow0 * sc0 + sum0;
        lrow1 = lrow1 * sc1 + sum1;

        // rescale O accumulators (register sc)
        #pragma unroll
        for (int nf = 0; nf < 8; nf++) {
            o_acc[nf][0] *= sc0; o_acc[nf][1] *= sc0;
            o_acc[nf][2] *= sc1; o_acc[nf][3] *= sc1;
        }

        __syncwarp();   // P stores visible to ldmatrix within the warp

        // ---- O += P @ V : 16x64 per warp ----
        #pragma unroll
        for (int ks = 0; ks < 8; ks++) {
            const int kk = ks << 3;
            uint32_t a[4];
            ldsm_x4(a, Ps_u32 + qoff + ks * 32);
            #pragma unroll
            for (int nf = 0; nf < 8; nf++) {
                uint32_t bb[2];
                bb[0] = __float_as_uint(Vb[(kk + tig    ) * 72 + nf * 8 + g]);
                bb[1] = __float_as_uint(Vb[(kk + tig + 4) * 72 + nf * 8 + g]);
                mma_tf32(o_acc[nf], a, bb);
            }
        }

        __syncthreads();   // all warps done with buf before overwrite

        c = nc;
        buf ^= 1;
    }

    const float inv0 = 1.0f / lrow0;
    const float inv1 = 1.0f / lrow1;
    #pragma unroll
    for (int nf = 0; nf < 8; nf++) {
        const int col = h * DKK + nf * 8 + 2 * tig;
        float* o0 = O + (size_t)(b * SS + qbase + m0 + g    ) * DD + col;
        float* o1 = O + (size_t)(b * SS + qbase + m0 + g + 8) * DD + col;
        *(float2*)o0 = make_float2(o_acc[nf][0] * inv0, o_acc[nf][1] * inv0);
        *(float2*)o1 = make_float2(o_acc[nf][2] * inv1, o_acc[nf][3] * inv1);
    }
}

// ---------------------------------------------------------------------------
// Launch
// ---------------------------------------------------------------------------
extern "C" void kernel_launch(void* const* d_in, const int* in_sizes, int n_in,
                              void* d_out, int out_size) {
    const float* x     = (const float*)d_in[0];
    const float* Wq    = (const float*)d_in[1];
    const float* bq    = (const float*)d_in[2];
    const float* Wk    = (const float*)d_in[3];
    const float* bk    = (const float*)d_in[4];
    const float* Wv    = (const float*)d_in[5];
    const float* bv    = (const float*)d_in[6];
    const float* Wo    = (const float*)d_in[7];
    const float* bo    = (const float*)d_in[8];
    const float* ln1_g = (const float*)d_in[9];
    const float* ln1_b = (const float*)d_in[10];
    const float* W1    = (const float*)d_in[11];
    const float* b1    = (const float*)d_in[12];
    const float* W2    = (const float*)d_in[13];
    const float* b2    = (const float*)d_in[14];
    const float* ln2_g = (const float*)d_in[15];
    const float* ln2_b = (const float*)d_in[16];
    float* out = (float*)d_out;

    float *xn, *qkv, *att, *x1, *xn2, *hbuf, *wqkv, *wo, *w1, *w2, *bqkv;
    cudaGetSymbolAddress((void**)&xn,   g_xn);
    cudaGetSymbolAddress((void**)&qkv,  g_qkv);
    cudaGetSymbolAddress((void**)&att,  g_att);
    cudaGetSymbolAddress((void**)&x1,   g_x1);
    cudaGetSymbolAddress((void**)&xn2,  g_xn2);
    cudaGetSymbolAddress((void**)&hbuf, g_h);
    cudaGetSymbolAddress((void**)&wqkv, g_wqkv);
    cudaGetSymbolAddress((void**)&wo,   g_wo);
    cudaGetSymbolAddress((void**)&w1,   g_w1);
    cudaGetSymbolAddress((void**)&w2,   g_w2);
    cudaGetSymbolAddress((void**)&bqkv, g_bqkv);

    cudaFuncSetAttribute(gemm_tf32_kernel<0>,
        cudaFuncAttributeMaxDynamicSharedMemorySize, GEMM_SMEM_BYTES);
    cudaFuncSetAttribute(gemm_tf32_kernel<1>,
        cudaFuncAttributeMaxDynamicSharedMemorySize, GEMM_SMEM_BYTES);
    cudaFuncSetAttribute(gemm_tf32_kernel<2>,
        cudaFuncAttributeMaxDynamicSharedMemorySize, GEMM_SMEM_BYTES);
    cudaFuncSetAttribute(attn_kernel,
        cudaFuncAttributeMaxDynamicSharedMemorySize, ATTN_SMEM_BYTES);

    // 0) fused prepass: round + concat weights (single launch, R12)
    prep_kernel<<<(PREP_TOTAL + 255) / 256, 256>>>(
        (const float4*)Wq, (const float4*)Wk, (const float4*)Wv,
        (const float4*)Wo, (const float4*)W1, (const float4*)W2,
        (const float4*)bq, (const float4*)bk, (const float4*)bv,
        (float4*)wqkv, (float4*)wo, (float4*)w1, (float4*)w2, (float4*)bqkv);

    // 1) xn = LN(x)
    ln_kernel<<<MM, 256>>>(x, ln1_g, ln1_b, xn);

    // 2) qkv = xn @ Wqkv + bqkv
    dim3 gq(3 * DD / 128, MM / 128);
    gemm_tf32_kernel<0><<<gq, 128, GEMM_SMEM_BYTES>>>(xn, wqkv, bqkv, nullptr,
                                                      qkv, MM, 3 * DD, DD);

    // 3) tensor-core masked attention (warp-local softmax)
    attn_kernel<<<dim3(SS / QT, HH, BB), 128, ATTN_SMEM_BYTES>>>(qkv, att);

    // 4) x1 = x + att @ Wo + bo
    dim3 g1(DD / 128, MM / 128);
    gemm_tf32_kernel<2><<<g1, 128, GEMM_SMEM_BYTES>>>(att, wo, bo, x, x1, MM, DD, DD);

    // 5) xn2 = LN(x1)
    ln_kernel<<<MM, 256>>>(x1, ln2_g, ln2_b, xn2);

    // 6) h = gelu(xn2 @ W1 + b1)
    dim3 g2(DFF / 128, MM / 128);
    gemm_tf32_kernel<1><<<g2, 128, GEMM_SMEM_BYTES>>>(xn2, w1, b1, nullptr, hbuf, MM, DFF, DD);

    // 7) out = x1 + h @ W2 + b2
    gemm_tf32_kernel<2><<<g1, 128, GEMM_SMEM_BYTES>>>(hbuf, w2, b2, x1, out, MM, DD, DFF);
}

// round 15
// speedup vs baseline: 1.0622x; 1.0426x over previous
#include <cuda_runtime.h>
#include <math.h>
#include <stdint.h>

// ---------------------------------------------------------------------------
// Problem constants
// ---------------------------------------------------------------------------
#define BB 2
#define SS 2048
#define DD 1024
#define HH 16
#define DKK 64
#define DFF 4096
#define WINDOW 128
#define NGLOBAL 16
#define MM (BB * SS)   // 4096 rows

// ---------------------------------------------------------------------------
// Scratch (device globals; no allocation allowed)
// ---------------------------------------------------------------------------
__device__ float g_xn  [MM * DD];
__device__ float g_qkv [MM * 3 * DD];
__device__ float g_att [MM * DD];
__device__ float g_x1  [MM * DD];
__device__ float g_xn2 [MM * DD];
__device__ float g_h   [MM * DFF];
__device__ float g_wqkv[DD * 3 * DD];
__device__ float g_wo  [DD * DD];
__device__ float g_w1  [DD * DFF];
__device__ float g_w2  [DFF * DD];
__device__ float g_bqkv[3 * DD];

// ---------------------------------------------------------------------------
// PTX helpers
// ---------------------------------------------------------------------------
__device__ __forceinline__ float round_tf32(float x) {
    uint32_t r;
    asm("cvt.rna.tf32.f32 %0, %1;" : "=r"(r) : "f"(x));
    return __uint_as_float(r);
}
__device__ __forceinline__ float4 rtf4(float4 v) {
    v.x = round_tf32(v.x); v.y = round_tf32(v.y);
    v.z = round_tf32(v.z); v.w = round_tf32(v.w);
    return v;
}

__device__ __forceinline__ void mma_tf32(float c[4], const uint32_t a[4], const uint32_t b[2]) {
    asm volatile(
        "mma.sync.aligned.m16n8k8.row.col.f32.tf32.tf32.f32 "
        "{%0,%1,%2,%3}, {%4,%5,%6,%7}, {%8,%9}, {%0,%1,%2,%3};\n"
        : "+f"(c[0]), "+f"(c[1]), "+f"(c[2]), "+f"(c[3])
        : "r"(a[0]), "r"(a[1]), "r"(a[2]), "r"(a[3]), "r"(b[0]), "r"(b[1]));
}

__device__ __forceinline__ void ldsm_x4(uint32_t r[4], uint32_t addr) {
    asm volatile("ldmatrix.sync.aligned.m8n8.x4.shared.b16 {%0,%1,%2,%3}, [%4];"
                 : "=r"(r[0]), "=r"(r[1]), "=r"(r[2]), "=r"(r[3]) : "r"(addr));
}

__device__ __forceinline__ void cp_async16(float* smem_dst, const float* gmem_src) {
    uint32_t s = (uint32_t)__cvta_generic_to_shared(smem_dst);
    asm volatile("cp.async.cg.shared.global [%0], [%1], 16;\n" :: "r"(s), "l"(gmem_src));
}
__device__ __forceinline__ void cp_async_commit() {
    asm volatile("cp.async.commit_group;\n");
}
template<int N>
__device__ __forceinline__ void cp_async_wait() {
    asm volatile("cp.async.wait_group %0;\n" :: "n"(N));
}

__device__ __forceinline__ float gelu_exact(float x) {
    return 0.5f * x * (1.0f + erff(x * 0.70710678118654752f));
}

// ---------------------------------------------------------------------------
// Fused prepass (R12): round weights to tf32, concat QKV weights + biases.
// ---------------------------------------------------------------------------
#define PREP_TOTAL 3146496
__global__ void __launch_bounds__(256) prep_kernel(
        const float4* __restrict__ Wq, const float4* __restrict__ Wk,
        const float4* __restrict__ Wv, const float4* __restrict__ Wo,
        const float4* __restrict__ W1, const float4* __restrict__ W2,
        const float4* __restrict__ bq, const float4* __restrict__ bk,
        const float4* __restrict__ bv,
        float4* __restrict__ wqkv, float4* __restrict__ wo,
        float4* __restrict__ w1, float4* __restrict__ w2,
        float4* __restrict__ bqkv) {
    int idx = blockIdx.x * 256 + threadIdx.x;
    if (idx < 786432) {
        int sub = idx >> 18;            // 0..2
        int k   = idx & 262143;
        int r   = k >> 8, c = k & 255;
        const float4* src = (sub == 0) ? Wq : (sub == 1) ? Wk : Wv;
        wqkv[r * 768 + sub * 256 + c] = rtf4(src[k]);
    } else if (idx < 1048576) {
        int k = idx - 786432;
        wo[k] = rtf4(Wo[k]);
    } else if (idx < 2097152) {
        int k = idx - 1048576;
        w1[k] = rtf4(W1[k]);
    } else if (idx < 3145728) {
        int k = idx - 2097152;
        w2[k] = rtf4(W2[k]);
    } else if (idx < PREP_TOTAL) {
        int k = idx - 3145728;          // 0..767
        int sub = k >> 8, c = k & 255;
        const float4* src = (sub == 0) ? bq : (sub == 1) ? bk : bv;
        bqkv[sub * 256 + c] = src[c];
    }
}

// ---------------------------------------------------------------------------
// LayerNorm: one block per row of 1024, 256 threads. Output tf32-rounded.
// ---------------------------------------------------------------------------
__device__ __forceinline__ float block_reduce_sum(float v, float* sh) {
    int lane = threadIdx.x & 31;
    int wid  = threadIdx.x >> 5;
    #pragma unroll
    for (int o = 16; o > 0; o >>= 1) v += __shfl_down_sync(0xffffffffu, v, o);
    if (lane == 0) sh[wid] = v;
    __syncthreads();
    if (wid == 0) {
        float t = (lane < 8) ? sh[lane] : 0.0f;
        #pragma unroll
        for (int o = 4; o > 0; o >>= 1) t += __shfl_down_sync(0xffffffffu, t, o);
        if (lane == 0) sh[0] = t;
    }
    __syncthreads();
    float r = sh[0];
    __syncthreads();
    return r;
}

__global__ void __launch_bounds__(256) ln_kernel(const float* __restrict__ x,
                                                 const float* __restrict__ g,
                                                 const float* __restrict__ b,
                                                 float* __restrict__ y) {
    __shared__ float sh[32];
    const int row = blockIdx.x;
    const float* xr = x + (size_t)row * DD;
    float v[4];
    float s = 0.0f;
    #pragma unroll
    for (int i = 0; i < 4; i++) { v[i] = xr[threadIdx.x + 256 * i]; s += v[i]; }
    s = block_reduce_sum(s, sh);
    const float mean = s * (1.0f / DD);
    float sq = 0.0f;
    #pragma unroll
    for (int i = 0; i < 4; i++) { float d = v[i] - mean; sq += d * d; }
    sq = block_reduce_sum(sq, sh);
    const float rstd = rsqrtf(sq * (1.0f / DD) + 1e-5f);
    float* yr = y + (size_t)row * DD;
    #pragma unroll
    for (int i = 0; i < 4; i++) {
        int c = threadIdx.x + 256 * i;
        yr[c] = round_tf32((v[i] - mean) * rstd * g[c] + b[c]);
    }
}

// ---------------------------------------------------------------------------
// TF32 tensor-core GEMM v4 (R12, proven): 128x128 CTA tile, 128 threads
// (4 warps, 2x2 of 64x64), A via ldmatrix, B scalar LDS, 2-stage ring,
// 3 CTAs/SM. For the big-N GEMMs (QKV N=3072, FFN1 N=4096).
// ---------------------------------------------------------------------------
#define AS_STRIDE 36
#define BS_STRIDE 136
#define AS_FLOATS (128 * AS_STRIDE)
#define BS_FLOATS (32 * BS_STRIDE)
#define STG_FLOATS (AS_FLOATS + BS_FLOATS)     // 8960
#define GEMM_SMEM_BYTES (2 * STG_FLOATS * 4)   // 71680

template<int EPI>
__global__ void __launch_bounds__(128, 3) gemm_tf32_kernel(
        const float* __restrict__ A, const float* __restrict__ B,
        const float* __restrict__ bias, const float* __restrict__ resid,
        float* __restrict__ C, int M, int N, int K) {
    extern __shared__ float smem[];
    const uint32_t smem_u32 = (uint32_t)__cvta_generic_to_shared(smem);

    const int bm = blockIdx.y * 128;
    const int bn = blockIdx.x * 128;
    const int tid  = threadIdx.x;
    const int warp = tid >> 5;
    const int lane = tid & 31;
    const int g    = lane >> 2;
    const int tig  = lane & 3;
    const int warp_m = (warp & 1) * 64;
    const int warp_n = (warp >> 1) * 64;

    const uint32_t aoff = (uint32_t)((warp_m + (lane & 15)) * AS_STRIDE * 4)
                        + ((lane & 16) ? 16u : 0u);

    float acc[4][8][4];
    #pragma unroll
    for (int mf = 0; mf < 4; mf++)
        #pragma unroll
        for (int nf = 0; nf < 8; nf++)
            #pragma unroll
            for (int r = 0; r < 4; r++) acc[mf][nf][r] = 0.0f;

    const int NK = K >> 5;

    auto load_tile = [&](int kt) {
        float* As = smem + (kt & 1) * STG_FLOATS;
        float* Bs = As + AS_FLOATS;
        const int k0 = kt << 5;
        #pragma unroll
        for (int i = 0; i < 8; i++) {
            int f = tid + 128 * i;
            int row = f >> 3, c4 = (f & 7) << 2;
            cp_async16(&As[row * AS_STRIDE + c4],
                       A + (size_t)(bm + row) * K + k0 + c4);
        }
        #pragma unroll
        for (int i = 0; i < 8; i++) {
            int f = tid + 128 * i;
            int row = f >> 5, c4 = (f & 31) << 2;
            cp_async16(&Bs[row * BS_STRIDE + c4],
                       B + (size_t)(k0 + row) * N + bn + c4);
        }
        cp_async_commit();
    };

    load_tile(0);
    load_tile(1);

    for (int kt = 0; kt < NK; kt++) {
        if (kt + 1 < NK) cp_async_wait<1>();
        else             cp_async_wait<0>();
        __syncthreads();

        const uint32_t As_u32 = smem_u32 + (kt & 1) * (STG_FLOATS * 4);
        const float* Bs = smem + (kt & 1) * STG_FLOATS + AS_FLOATS;

        #pragma unroll
        for (int ks = 0; ks < 4; ks++) {
            const int kk = ks << 3;
            uint32_t afrag[4][4];
            #pragma unroll
            for (int mf = 0; mf < 4; mf++)
                ldsm_x4(afrag[mf], As_u32 + aoff + mf * (16 * AS_STRIDE * 4) + ks * 32);
            #pragma unroll
            for (int half = 0; half < 2; half++) {
                uint32_t bfrag[4][2];
                #pragma unroll
                for (int nf = 0; nf < 4; nf++) {
                    const int c0 = warp_n + (half * 4 + nf) * 8 + g;
                    bfrag[nf][0] = __float_as_uint(Bs[(kk + tig    ) * BS_STRIDE + c0]);
                    bfrag[nf][1] = __float_as_uint(Bs[(kk + tig + 4) * BS_STRIDE + c0]);
                }
                #pragma unroll
                for (int mf = 0; mf < 4; mf++)
                    #pragma unroll
                    for (int nf = 0; nf < 4; nf++)
                        mma_tf32(acc[mf][half * 4 + nf], afrag[mf], bfrag[nf]);
            }
        }

        __syncthreads();
        if (kt + 2 < NK) load_tile(kt + 2);
    }

    #pragma unroll
    for (int mf = 0; mf < 4; mf++) {
        #pragma unroll
        for (int nf = 0; nf < 8; nf++) {
            const int row0 = bm + warp_m + mf * 16 + g;
            const int row1 = row0 + 8;
            const int col  = bn + warp_n + nf * 8 + 2 * tig;
            const float b0 = bias[col], b1 = bias[col + 1];
            float v0 = acc[mf][nf][0] + b0;
            float v1 = acc[mf][nf][1] + b1;
            float v2 = acc[mf][nf][2] + b0;
            float v3 = acc[mf][nf][3] + b1;
            if (EPI == 1) {
                v0 = round_tf32(gelu_exact(v0)); v1 = round_tf32(gelu_exact(v1));
                v2 = round_tf32(gelu_exact(v2)); v3 = round_tf32(gelu_exact(v3));
            }
            if (EPI == 2) {
                float2 r0v = *(const float2*)(resid + (size_t)row0 * N + col);
                float2 r1v = *(const float2*)(resid + (size_t)row1 * N + col);
                v0 += r0v.x; v1 += r0v.y; v2 += r1v.x; v3 += r1v.y;
            }
            *(float2*)(C + (size_t)row0 * N + col) = make_float2(v0, v1);
            *(float2*)(C + (size_t)row1 * N + col) = make_float2(v2, v3);
        }
    }
}

// ---------------------------------------------------------------------------
// TF32 GEMM n64 variant: 128x64 CTA tile for the N=1024 GEMMs (Wo, FFN2).
// 512 CTAs instead of 256 -> 4 CTAs/SM (16 warps) at ~0.86 wave fill.
// 4 warps, 2x2 of 64x32 warp tiles. Same math/K order as v4 (bit-identical
// per-element results). B smem stride 72 (=8 mod 32 banks, conflict-free).
// ---------------------------------------------------------------------------
#define BS2_STRIDE 72
#define BS2_FLOATS (32 * BS2_STRIDE)                 // 2304
#define STG2_FLOATS (AS_FLOATS + BS2_FLOATS)         // 6912
#define GEMM64_SMEM_BYTES (2 * STG2_FLOATS * 4)      // 55296

template<int EPI>
__global__ void __launch_bounds__(128, 4) gemm_tf32_n64_kernel(
        const float* __restrict__ A, const float* __restrict__ B,
        const float* __restrict__ bias, const float* __restrict__ resid,
        float* __restrict__ C, int M, int N, int K) {
    extern __shared__ float smem[];
    const uint32_t smem_u32 = (uint32_t)__cvta_generic_to_shared(smem);

    const int bm = blockIdx.y * 128;
    const int bn = blockIdx.x * 64;
    const int tid  = threadIdx.x;
    const int warp = tid >> 5;
    const int lane = tid & 31;
    const int g    = lane >> 2;
    const int tig  = lane & 3;
    const int warp_m = (warp & 1) * 64;
    const int warp_n = (warp >> 1) * 32;

    const uint32_t aoff = (uint32_t)((warp_m + (lane & 15)) * AS_STRIDE * 4)
                        + ((lane & 16) ? 16u : 0u);

    float acc[4][4][4];
    #pragma unroll
    for (int mf = 0; mf < 4; mf++)
        #pragma unroll
        for (int nf = 0; nf < 4; nf++)
            #pragma unroll
            for (int r = 0; r < 4; r++) acc[mf][nf][r] = 0.0f;

    const int NK = K >> 5;

    auto load_tile = [&](int kt) {
        float* As = smem + (kt & 1) * STG2_FLOATS;
        float* Bs = As + AS_FLOATS;
        const int k0 = kt << 5;
        #pragma unroll
        for (int i = 0; i < 8; i++) {
            int f = tid + 128 * i;
            int row = f >> 3, c4 = (f & 7) << 2;
            cp_async16(&As[row * AS_STRIDE + c4],
                       A + (size_t)(bm + row) * K + k0 + c4);
        }
        #pragma unroll
        for (int i = 0; i < 4; i++) {
            int f = tid + 128 * i;
            int row = f >> 4, c4 = (f & 15) << 2;
            cp_async16(&Bs[row * BS2_STRIDE + c4],
                       B + (size_t)(k0 + row) * N + bn + c4);
        }
        cp_async_commit();
    };

    load_tile(0);
    load_tile(1);

    for (int kt = 0; kt < NK; kt++) {
        if (kt + 1 < NK) cp_async_wait<1>();
        else             cp_async_wait<0>();
        __syncthreads();

        const uint32_t As_u32 = smem_u32 + (kt & 1) * (STG2_FLOATS * 4);
        const float* Bs = smem + (kt & 1) * STG2_FLOATS + AS_FLOATS;

        #pragma unroll
        for (int ks = 0; ks < 4; ks++) {
            const int kk = ks << 3;
            uint32_t afrag[4][4];
            #pragma unroll
            for (int mf = 0; mf < 4; mf++)
                ldsm_x4(afrag[mf], As_u32 + aoff + mf * (16 * AS_STRIDE * 4) + ks * 32);
            uint32_t bfrag[4][2];
            #pragma unroll
            for (int nf = 0; nf < 4; nf++) {
                const int c0 = warp_n + nf * 8 + g;
                bfrag[nf][0] = __float_as_uint(Bs[(kk + tig    ) * BS2_STRIDE + c0]);
                bfrag[nf][1] = __float_as_uint(Bs[(kk + tig + 4) * BS2_STRIDE + c0]);
            }
            #pragma unroll
            for (int mf = 0; mf < 4; mf++)
                #pragma unroll
                for (int nf = 0; nf < 4; nf++)
                    mma_tf32(acc[mf][nf], afrag[mf], bfrag[nf]);
        }

        __syncthreads();
        if (kt + 2 < NK) load_tile(kt + 2);
    }

    #pragma unroll
    for (int mf = 0; mf < 4; mf++) {
        #pragma unroll
        for (int nf = 0; nf < 4; nf++) {
            const int row0 = bm + warp_m + mf * 16 + g;
            const int row1 = row0 + 8;
            const int col  = bn + warp_n + nf * 8 + 2 * tig;
            const float b0 = bias[col], b1 = bias[col + 1];
            float v0 = acc[mf][nf][0] + b0;
            float v1 = acc[mf][nf][1] + b1;
            float v2 = acc[mf][nf][2] + b0;
            float v3 = acc[mf][nf][3] + b1;
            if (EPI == 1) {
                v0 = round_tf32(gelu_exact(v0)); v1 = round_tf32(gelu_exact(v1));
                v2 = round_tf32(gelu_exact(v2)); v3 = round_tf32(gelu_exact(v3));
            }
            if (EPI == 2) {
                float2 r0v = *(const float2*)(resid + (size_t)row0 * N + col);
                float2 r1v = *(const float2*)(resid + (size_t)row1 * N + col);
                v0 += r0v.x; v1 += r0v.y; v2 += r1v.x; v3 += r1v.y;
            }
            *(float2*)(C + (size_t)row0 * N + col) = make_float2(v0, v1);
            *(float2*)(C + (size_t)row1 * N + col) = make_float2(v2, v3);
        }
    }
}

// ---------------------------------------------------------------------------
// Tensor-core masked flash attention v6 (R12, proven).
// ---------------------------------------------------------------------------
#define QT 64
#define CH 64
#define O_QS  0                        // [64][68]
#define O_KS  4352                     // 2 x [64][68]
#define O_VS  13056                    // 2 x [64][72]
#define O_PS  22272                    // [64][68]
#define O_RED 26624                    // [64][2]
#define O_M   26752                    // [64]
#define O_L   26816                    // [64]
#define O_SC  26880                    // [64]
#define ATTN_SMEM_FLOATS 26944
#define ATTN_SMEM_BYTES (ATTN_SMEM_FLOATS * 4)   // 107776

__global__ void __launch_bounds__(256) attn_kernel(
        const float* __restrict__ QKV, float* __restrict__ O) {
    extern __shared__ float dyn[];
    float* Qs  = dyn + O_QS;
    float* Ks  = dyn + O_KS;
    float* Vs  = dyn + O_VS;
    float* Ps  = dyn + O_PS;
    float* red = dyn + O_RED;
    float* mS  = dyn + O_M;
    float* lS  = dyn + O_L;
    float* scS = dyn + O_SC;
    const uint32_t dyn_u32 = (uint32_t)__cvta_generic_to_shared(dyn);

    const int qbase = blockIdx.x * QT;
    const int h  = blockIdx.y;
    const int b  = blockIdx.z;
    const int tid = threadIdx.x;
    const int warp = tid >> 5, lane = tid & 31;
    const int g = lane >> 2, tig = lane & 3;
    const int m0 = (warp >> 1) * 16;
    const int n0 = (warp & 1) * 32;
    const int w2 = warp & 1;
    const int pairbar = (warp >> 1) + 1;

    #define PAIR_BAR() asm volatile("bar.sync %0, 64;" :: "r"(pairbar) : "memory")

    const int RS = 3 * DD;
    const uint32_t qoff = (uint32_t)((m0 + (lane & 15)) * 68 * 4)
                        + ((lane & 16) ? 16u : 0u);
    const uint32_t koff = (uint32_t)((n0 + (lane & 7)) * 68 * 4)
                        + ((lane & 8) ? 16u : 0u)
                        + ((lane & 16) ? (uint32_t)(8 * 68 * 4) : 0u);
    const uint32_t Ps_u32 = dyn_u32 + O_PS * 4;

    int clo = max(0, (qbase - WINDOW) >> 6);
    int chi = min(SS / CH - 1, (qbase + QT - 1 + WINDOW) >> 6);
    if (qbase < NGLOBAL) { clo = 0; chi = SS / CH - 1; }

    auto load_kv = [&](int cc, int bf) {
        const int r = tid >> 4, d4 = tid & 15;
        float* Kb = Ks + bf * 4352;
        float* Vb = Vs + bf * 4608;
        #pragma unroll
        for (int it = 0; it < 4; it++) {
            int rr = r + it * 16;
            const float* src = QKV + (size_t)(b * SS + CH * cc + rr) * RS + h * DKK + d4 * 4;
            cp_async16(Kb + rr * 68 + d4 * 4, src + DD);
            cp_async16(Vb + rr * 72 + d4 * 4, src + 2 * DD);
        }
        cp_async_commit();
    };

    {
        const int r = tid >> 4, d4 = tid & 15;
        #pragma unroll
        for (int it = 0; it < 4; it++) {
            int qi = r + it * 16;
            cp_async16(Qs + qi * 68 + d4 * 4,
                       QKV + (size_t)(b * SS + qbase + qi) * RS + h * DKK + d4 * 4);
        }
        cp_async_commit();
    }
    load_kv(0, 0);

    if (tid < QT) { mS[tid] = -INFINITY; lS[tid] = 0.0f; }

    float o_acc[4][4];
    #pragma unroll
    for (int nf = 0; nf < 4; nf++)
        #pragma unroll
        for (int r = 0; r < 4; r++) o_acc[nf][r] = 0.0f;

    const int i0 = qbase + m0 + g;
    const int i1 = i0 + 8;
    const bool gi0 = (i0 < NGLOBAL);
    const bool gi1 = (i1 < NGLOBAL);

    int c = 0, buf = 0;
    while (c >= 0) {
        int nc;
        if (c == 0) nc = (clo > 0) ? clo : (chi >= 1 ? 1 : -1);
        else        nc = (c + 1 <= chi) ? c + 1 : -1;

        if (nc >= 0) {
            load_kv(nc, buf ^ 1);
            cp_async_wait<1>();
        } else {
            cp_async_wait<0>();
        }
        __syncthreads();

        const uint32_t Kb_u32 = dyn_u32 + (O_KS + buf * 4352) * 4;
        const float* Vb = Vs + buf * 4608;

        float s[4][4];
        #pragma unroll
        for (int nf = 0; nf < 4; nf++)
            #pragma unroll
            for (int r = 0; r < 4; r++) s[nf][r] = 0.0f;
        #pragma unroll
        for (int ks = 0; ks < 8; ks++) {
            uint32_t a[4];
            ldsm_x4(a, dyn_u32 + qoff + ks * 32);
            #pragma unroll
            for (int np = 0; np < 2; np++) {
                uint32_t bb4[4];
                ldsm_x4(bb4, Kb_u32 + koff + np * (16 * 68 * 4) + ks * 32);
                mma_tf32(s[2 * np    ], a, bb4    );
                mma_tf32(s[2 * np + 1], a, bb4 + 2);
            }
        }

        float mx0 = -INFINITY, mx1 = -INFINITY;
        #pragma unroll
        for (int nf = 0; nf < 4; nf++) {
            const int j0 = CH * c + n0 + nf * 8 + 2 * tig;
            const int j1 = j0 + 1;
            const bool vj0 = (j0 < NGLOBAL), vj1 = (j1 < NGLOBAL);
            s[nf][0] = (gi0 || vj0 || abs(i0 - j0) <= WINDOW) ? s[nf][0] * 0.125f : -INFINITY;
            s[nf][1] = (gi0 || vj1 || abs(i0 - j1) <= WINDOW) ? s[nf][1] * 0.125f : -INFINITY;
            s[nf][2] = (gi1 || vj0 || abs(i1 - j0) <= WINDOW) ? s[nf][2] * 0.125f : -INFINITY;
            s[nf][3] = (gi1 || vj1 || abs(i1 - j1) <= WINDOW) ? s[nf][3] * 0.125f : -INFINITY;
            mx0 = fmaxf(mx0, fmaxf(s[nf][0], s[nf][1]));
            mx1 = fmaxf(mx1, fmaxf(s[nf][2], s[nf][3]));
        }
        mx0 = fmaxf(mx0, __shfl_xor_sync(0xffffffffu, mx0, 1));
        mx0 = fmaxf(mx0, __shfl_xor_sync(0xffffffffu, mx0, 2));
        mx1 = fmaxf(mx1, __shfl_xor_sync(0xffffffffu, mx1, 1));
        mx1 = fmaxf(mx1, __shfl_xor_sync(0xffffffffu, mx1, 2));
        if (tig == 0) {
            red[(m0 + g    ) * 2 + w2] = mx0;
            red[(m0 + g + 8) * 2 + w2] = mx1;
        }
        PAIR_BAR();

        if (w2 == 0 && tig == 0) {
            const int r0 = m0 + g, r1 = m0 + g + 8;
            float mn0 = fmaxf(fmaxf(red[r0 * 2], red[r0 * 2 + 1]), mS[r0]);
            scS[r0] = __expf(mS[r0] - mn0);
            mS[r0]  = mn0;
            float mn1 = fmaxf(fmaxf(red[r1 * 2], red[r1 * 2 + 1]), mS[r1]);
            scS[r1] = __expf(mS[r1] - mn1);
            mS[r1]  = mn1;
        }
        PAIR_BAR();

        const float m0v = mS[m0 + g], m1v = mS[m0 + g + 8];
        float sum0 = 0.0f, sum1 = 0.0f;
        #pragma unroll
        for (int nf = 0; nf < 4; nf++) {
            s[nf][0] = __expf(s[nf][0] - m0v);
            s[nf][1] = __expf(s[nf][1] - m0v);
            s[nf][2] = __expf(s[nf][2] - m1v);
            s[nf][3] = __expf(s[nf][3] - m1v);
            sum0 += s[nf][0] + s[nf][1];
            sum1 += s[nf][2] + s[nf][3];
            const int col = n0 + nf * 8 + 2 * tig;
            *(float2*)&Ps[(m0 + g    ) * 68 + col] = make_float2(s[nf][0], s[nf][1]);
            *(float2*)&Ps[(m0 + g + 8) * 68 + col] = make_float2(s[nf][2], s[nf][3]);
        }
        sum0 += __shfl_xor_sync(0xffffffffu, sum0, 1);
        sum0 += __shfl_xor_sync(0xffffffffu, sum0, 2);
        sum1 += __shfl_xor_sync(0xffffffffu, sum1, 1);
        sum1 += __shfl_xor_sync(0xffffffffu, sum1, 2);
        if (tig == 0) {
            red[(m0 + g    ) * 2 + w2] = sum0;
            red[(m0 + g + 8) * 2 + w2] = sum1;
        }
        {
            const float sc0 = scS[m0 + g], sc1 = scS[m0 + g + 8];
            #pragma unroll
            for (int nf = 0; nf < 4; nf++) {
                o_acc[nf][0] *= sc0; o_acc[nf][1] *= sc0;
                o_acc[nf][2] *= sc1; o_acc[nf][3] *= sc1;
            }
        }
        PAIR_BAR();

        if (w2 == 0 && tig == 0) {
            const int r0 = m0 + g, r1 = m0 + g + 8;
            lS[r0] = lS[r0] * scS[r0] + red[r0 * 2] + red[r0 * 2 + 1];
            lS[r1] = lS[r1] * scS[r1] + red[r1 * 2] + red[r1 * 2 + 1];
        }

        #pragma unroll
        for (int ks = 0; ks < 8; ks++) {
            const int kk = ks << 3;
            uint32_t a[4];
            ldsm_x4(a, Ps_u32 + qoff + ks * 32);
            #pragma unroll
            for (int nf = 0; nf < 4; nf++) {
                uint32_t bb[2];
                bb[0] = __float_as_uint(Vb[(kk + tig    ) * 72 + n0 + nf * 8 + g]);
                bb[1] = __float_as_uint(Vb[(kk + tig + 4) * 72 + n0 + nf * 8 + g]);
                mma_tf32(o_acc[nf], a, bb);
            }
        }

        __syncthreads();

        c = nc;
        buf ^= 1;
    }

    const float inv0 = 1.0f / lS[m0 + g];
    const float inv1 = 1.0f / lS[m0 + g + 8];
    #pragma unroll
    for (int nf = 0; nf < 4; nf++) {
        const int col = h * DKK + n0 + nf * 8 + 2 * tig;
        float* o0 = O + (size_t)(b * SS + qbase + m0 + g    ) * DD + col;
        float* o1 = O + (size_t)(b * SS + qbase + m0 + g + 8) * DD + col;
        *(float2*)o0 = make_float2(o_acc[nf][0] * inv0, o_acc[nf][1] * inv0);
        *(float2*)o1 = make_float2(o_acc[nf][2] * inv1, o_acc[nf][3] * inv1);
    }
    #undef PAIR_BAR
}

// ---------------------------------------------------------------------------
// Launch
// ---------------------------------------------------------------------------
extern "C" void kernel_launch(void* const* d_in, const int* in_sizes, int n_in,
                              void* d_out, int out_size) {
    const float* x     = (const float*)d_in[0];
    const float* Wq    = (const float*)d_in[1];
    const float* bq    = (const float*)d_in[2];
    const float* Wk    = (const float*)d_in[3];
    const float* bk    = (const float*)d_in[4];
    const float* Wv    = (const float*)d_in[5];
    const float* bv    = (const float*)d_in[6];
    const float* Wo    = (const float*)d_in[7];
    const float* bo    = (const float*)d_in[8];
    const float* ln1_g = (const float*)d_in[9];
    const float* ln1_b = (const float*)d_in[10];
    const float* W1    = (const float*)d_in[11];
    const float* b1    = (const float*)d_in[12];
    const float* W2    = (const float*)d_in[13];
    const float* b2    = (const float*)d_in[14];
    const float* ln2_g = (const float*)d_in[15];
    const float* ln2_b = (const float*)d_in[16];
    float* out = (float*)d_out;

    float *xn, *qkv, *att, *x1, *xn2, *hbuf, *wqkv, *wo, *w1, *w2, *bqkv;
    cudaGetSymbolAddress((void**)&xn,   g_xn);
    cudaGetSymbolAddress((void**)&qkv,  g_qkv);
    cudaGetSymbolAddress((void**)&att,  g_att);
    cudaGetSymbolAddress((void**)&x1,   g_x1);
    cudaGetSymbolAddress((void**)&xn2,  g_xn2);
    cudaGetSymbolAddress((void**)&hbuf, g_h);
    cudaGetSymbolAddress((void**)&wqkv, g_wqkv);
    cudaGetSymbolAddress((void**)&wo,   g_wo);
    cudaGetSymbolAddress((void**)&w1,   g_w1);
    cudaGetSymbolAddress((void**)&w2,   g_w2);
    cudaGetSymbolAddress((void**)&bqkv, g_bqkv);

    cudaFuncSetAttribute(gemm_tf32_kernel<0>,
        cudaFuncAttributeMaxDynamicSharedMemorySize, GEMM_SMEM_BYTES);
    cudaFuncSetAttribute(gemm_tf32_kernel<1>,
        cudaFuncAttributeMaxDynamicSharedMemorySize, GEMM_SMEM_BYTES);
    cudaFuncSetAttribute(gemm_tf32_kernel<2>,
        cudaFuncAttributeMaxDynamicSharedMemorySize, GEMM_SMEM_BYTES);
    cudaFuncSetAttribute(gemm_tf32_n64_kernel<2>,
        cudaFuncAttributeMaxDynamicSharedMemorySize, GEMM64_SMEM_BYTES);
    cudaFuncSetAttribute(attn_kernel,
        cudaFuncAttributeMaxDynamicSharedMemorySize, ATTN_SMEM_BYTES);

    // 0) fused prepass: round + concat weights
    prep_kernel<<<(PREP_TOTAL + 255) / 256, 256>>>(
        (const float4*)Wq, (const float4*)Wk, (const float4*)Wv,
        (const float4*)Wo, (const float4*)W1, (const float4*)W2,
        (const float4*)bq, (const float4*)bk, (const float4*)bv,
        (float4*)wqkv, (float4*)wo, (float4*)w1, (float4*)w2, (float4*)bqkv);

    // 1) xn = LN(x)
    ln_kernel<<<MM, 256>>>(x, ln1_g, ln1_b, xn);

    // 2) qkv = xn @ Wqkv + bqkv  (n128 kernel: 768 CTAs, good fill)
    dim3 gq(3 * DD / 128, MM / 128);
    gemm_tf32_kernel<0><<<gq, 128, GEMM_SMEM_BYTES>>>(xn, wqkv, bqkv, nullptr,
                                                      qkv, MM, 3 * DD, DD);

    // 3) tensor-core masked attention (R12)
    attn_kernel<<<dim3(SS / QT, HH, BB), 256, ATTN_SMEM_BYTES>>>(qkv, att);

    // 4) x1 = x + att @ Wo + bo   (n64 kernel: 512 CTAs, 4 CTAs/SM)
    dim3 g64(DD / 64, MM / 128);
    gemm_tf32_n64_kernel<2><<<g64, 128, GEMM64_SMEM_BYTES>>>(att, wo, bo, x, x1, MM, DD, DD);

    // 5) xn2 = LN(x1)
    ln_kernel<<<MM, 256>>>(x1, ln2_g, ln2_b, xn2);

    // 6) h = gelu(xn2 @ W1 + b1)  (n128 kernel: 1024 CTAs)
    dim3 g2(DFF / 128, MM / 128);
    gemm_tf32_kernel<1><<<g2, 128, GEMM_SMEM_BYTES>>>(xn2, w1, b1, nullptr, hbuf, MM, DFF, DD);

    // 7) out = x1 + h @ W2 + b2   (n64 kernel: 512 CTAs, 4 CTAs/SM)
    gemm_tf32_n64_kernel<2><<<g64, 128, GEMM64_SMEM_BYTES>>>(hbuf, w2, b2, x1, out, MM, DD, DFF);
}

// round 16
// speedup vs baseline: 1.0731x; 1.0103x over previous
#include <cuda_runtime.h>
#include <math.h>
#include <stdint.h>

// ---------------------------------------------------------------------------
// Problem constants
// ---------------------------------------------------------------------------
#define BB 2
#define SS 2048
#define DD 1024
#define HH 16
#define DKK 64
#define DFF 4096
#define WINDOW 128
#define NGLOBAL 16
#define MM (BB * SS)   // 4096 rows

// ---------------------------------------------------------------------------
// Scratch (device globals; no allocation allowed)
// ---------------------------------------------------------------------------
__device__ float g_xn  [MM * DD];
__device__ float g_qkv [MM * 3 * DD];
__device__ float g_att [MM * DD];
__device__ float g_x1  [MM * DD];
__device__ float g_xn2 [MM * DD];
__device__ float g_h   [MM * DFF];
__device__ float g_wqkv[DD * 3 * DD];
__device__ float g_bqkv[3 * DD];

// ---------------------------------------------------------------------------
// PTX helpers
// ---------------------------------------------------------------------------
__device__ __forceinline__ void mma_tf32(float c[4], const uint32_t a[4], const uint32_t b[2]) {
    asm volatile(
        "mma.sync.aligned.m16n8k8.row.col.f32.tf32.tf32.f32 "
        "{%0,%1,%2,%3}, {%4,%5,%6,%7}, {%8,%9}, {%0,%1,%2,%3};\n"
        : "+f"(c[0]), "+f"(c[1]), "+f"(c[2]), "+f"(c[3])
        : "r"(a[0]), "r"(a[1]), "r"(a[2]), "r"(a[3]), "r"(b[0]), "r"(b[1]));
}

__device__ __forceinline__ void ldsm_x4(uint32_t r[4], uint32_t addr) {
    asm volatile("ldmatrix.sync.aligned.m8n8.x4.shared.b16 {%0,%1,%2,%3}, [%4];"
                 : "=r"(r[0]), "=r"(r[1]), "=r"(r[2]), "=r"(r[3]) : "r"(addr));
}

__device__ __forceinline__ void cp_async16(float* smem_dst, const float* gmem_src) {
    uint32_t s = (uint32_t)__cvta_generic_to_shared(smem_dst);
    asm volatile("cp.async.cg.shared.global [%0], [%1], 16;\n" :: "r"(s), "l"(gmem_src));
}
__device__ __forceinline__ void cp_async_commit() {
    asm volatile("cp.async.commit_group;\n");
}
template<int N>
__device__ __forceinline__ void cp_async_wait() {
    asm volatile("cp.async.wait_group %0;\n" :: "n"(N));
}

__device__ __forceinline__ float gelu_exact(float x) {
    return 0.5f * x * (1.0f + erff(x * 0.70710678118654752f));
}

// ---------------------------------------------------------------------------
// Prepass: concat QKV weights + biases only (raw fp32 copy — the tf32 mma
// truncates operands in hardware, so pre-rounding is unnecessary work).
// Wo/W1/W2/bo/b1/b2 are consumed directly from the inputs.
// ---------------------------------------------------------------------------
#define PREP_TOTAL 787200    // 786432 weight float4s + 768 bias float4s
__global__ void __launch_bounds__(256) prep_kernel(
        const float4* __restrict__ Wq, const float4* __restrict__ Wk,
        const float4* __restrict__ Wv,
        const float4* __restrict__ bq, const float4* __restrict__ bk,
        const float4* __restrict__ bv,
        float4* __restrict__ wqkv, float4* __restrict__ bqkv) {
    int idx = blockIdx.x * 256 + threadIdx.x;
    if (idx < 786432) {
        int sub = idx >> 18;            // 0..2
        int k   = idx & 262143;
        int r   = k >> 8, c = k & 255;
        const float4* src = (sub == 0) ? Wq : (sub == 1) ? Wk : Wv;
        wqkv[r * 768 + sub * 256 + c] = src[k];
    } else if (idx < PREP_TOTAL) {
        int k = idx - 786432;           // 0..767
        int sub = k >> 8, c = k & 255;
        const float4* src = (sub == 0) ? bq : (sub == 1) ? bk : bv;
        bqkv[sub * 256 + c] = src[c];
    }
}

// ---------------------------------------------------------------------------
// LayerNorm: one block per row of 1024, 256 threads.
// ---------------------------------------------------------------------------
__device__ __forceinline__ float block_reduce_sum(float v, float* sh) {
    int lane = threadIdx.x & 31;
    int wid  = threadIdx.x >> 5;
    #pragma unroll
    for (int o = 16; o > 0; o >>= 1) v += __shfl_down_sync(0xffffffffu, v, o);
    if (lane == 0) sh[wid] = v;
    __syncthreads();
    if (wid == 0) {
        float t = (lane < 8) ? sh[lane] : 0.0f;
        #pragma unroll
        for (int o = 4; o > 0; o >>= 1) t += __shfl_down_sync(0xffffffffu, t, o);
        if (lane == 0) sh[0] = t;
    }
    __syncthreads();
    float r = sh[0];
    __syncthreads();
    return r;
}

__global__ void __launch_bounds__(256) ln_kernel(const float* __restrict__ x,
                                                 const float* __restrict__ g,
                                                 const float* __restrict__ b,
                                                 float* __restrict__ y) {
    __shared__ float sh[32];
    const int row = blockIdx.x;
    const float* xr = x + (size_t)row * DD;
    float v[4];
    float s = 0.0f;
    #pragma unroll
    for (int i = 0; i < 4; i++) { v[i] = xr[threadIdx.x + 256 * i]; s += v[i]; }
    s = block_reduce_sum(s, sh);
    const float mean = s * (1.0f / DD);
    float sq = 0.0f;
    #pragma unroll
    for (int i = 0; i < 4; i++) { float d = v[i] - mean; sq += d * d; }
    sq = block_reduce_sum(sq, sh);
    const float rstd = rsqrtf(sq * (1.0f / DD) + 1e-5f);
    float* yr = y + (size_t)row * DD;
    #pragma unroll
    for (int i = 0; i < 4; i++) {
        int c = threadIdx.x + 256 * i;
        yr[c] = (v[i] - mean) * rstd * g[c] + b[c];
    }
}

// ---------------------------------------------------------------------------
// TF32 tensor-core GEMM v4 (R12/R15 proven): 128x128 CTA tile, 128 threads
// (4 warps, 2x2 of 64x64), A via ldmatrix, B scalar LDS, 2-stage ring,
// 3 CTAs/SM. For the big-N GEMMs (QKV N=3072, FFN1 N=4096).
// ---------------------------------------------------------------------------
#define AS_STRIDE 36
#define BS_STRIDE 136
#define AS_FLOATS (128 * AS_STRIDE)
#define BS_FLOATS (32 * BS_STRIDE)
#define STG_FLOATS (AS_FLOATS + BS_FLOATS)     // 8960
#define GEMM_SMEM_BYTES (2 * STG_FLOATS * 4)   // 71680

template<int EPI>
__global__ void __launch_bounds__(128, 3) gemm_tf32_kernel(
        const float* __restrict__ A, const float* __restrict__ B,
        const float* __restrict__ bias, const float* __restrict__ resid,
        float* __restrict__ C, int M, int N, int K) {
    extern __shared__ float smem[];
    const uint32_t smem_u32 = (uint32_t)__cvta_generic_to_shared(smem);

    const int bm = blockIdx.y * 128;
    const int bn = blockIdx.x * 128;
    const int tid  = threadIdx.x;
    const int warp = tid >> 5;
    const int lane = tid & 31;
    const int g    = lane >> 2;
    const int tig  = lane & 3;
    const int warp_m = (warp & 1) * 64;
    const int warp_n = (warp >> 1) * 64;

    const uint32_t aoff = (uint32_t)((warp_m + (lane & 15)) * AS_STRIDE * 4)
                        + ((lane & 16) ? 16u : 0u);

    float acc[4][8][4];
    #pragma unroll
    for (int mf = 0; mf < 4; mf++)
        #pragma unroll
        for (int nf = 0; nf < 8; nf++)
            #pragma unroll
            for (int r = 0; r < 4; r++) acc[mf][nf][r] = 0.0f;

    const int NK = K >> 5;

    auto load_tile = [&](int kt) {
        float* As = smem + (kt & 1) * STG_FLOATS;
        float* Bs = As + AS_FLOATS;
        const int k0 = kt << 5;
        #pragma unroll
        for (int i = 0; i < 8; i++) {
            int f = tid + 128 * i;
            int row = f >> 3, c4 = (f & 7) << 2;
            cp_async16(&As[row * AS_STRIDE + c4],
                       A + (size_t)(bm + row) * K + k0 + c4);
        }
        #pragma unroll
        for (int i = 0; i < 8; i++) {
            int f = tid + 128 * i;
            int row = f >> 5, c4 = (f & 31) << 2;
            cp_async16(&Bs[row * BS_STRIDE + c4],
                       B + (size_t)(k0 + row) * N + bn + c4);
        }
        cp_async_commit();
    };

    load_tile(0);
    load_tile(1);

    for (int kt = 0; kt < NK; kt++) {
        if (kt + 1 < NK) cp_async_wait<1>();
        else             cp_async_wait<0>();
        __syncthreads();

        const uint32_t As_u32 = smem_u32 + (kt & 1) * (STG_FLOATS * 4);
        const float* Bs = smem + (kt & 1) * STG_FLOATS + AS_FLOATS;

        #pragma unroll
        for (int ks = 0; ks < 4; ks++) {
            const int kk = ks << 3;
            uint32_t afrag[4][4];
            #pragma unroll
            for (int mf = 0; mf < 4; mf++)
                ldsm_x4(afrag[mf], As_u32 + aoff + mf * (16 * AS_STRIDE * 4) + ks * 32);
            #pragma unroll
            for (int half = 0; half < 2; half++) {
                uint32_t bfrag[4][2];
                #pragma unroll
                for (int nf = 0; nf < 4; nf++) {
                    const int c0 = warp_n + (half * 4 + nf) * 8 + g;
                    bfrag[nf][0] = __float_as_uint(Bs[(kk + tig    ) * BS_STRIDE + c0]);
                    bfrag[nf][1] = __float_as_uint(Bs[(kk + tig + 4) * BS_STRIDE + c0]);
                }
                #pragma unroll
                for (int mf = 0; mf < 4; mf++)
                    #pragma unroll
                    for (int nf = 0; nf < 4; nf++)
                        mma_tf32(acc[mf][half * 4 + nf], afrag[mf], bfrag[nf]);
            }
        }

        __syncthreads();
        if (kt + 2 < NK) load_tile(kt + 2);
    }

    #pragma unroll
    for (int mf = 0; mf < 4; mf++) {
        #pragma unroll
        for (int nf = 0; nf < 8; nf++) {
            const int row0 = bm + warp_m + mf * 16 + g;
            const int row1 = row0 + 8;
            const int col  = bn + warp_n + nf * 8 + 2 * tig;
            const float b0 = bias[col], b1 = bias[col + 1];
            float v0 = acc[mf][nf][0] + b0;
            float v1 = acc[mf][nf][1] + b1;
            float v2 = acc[mf][nf][2] + b0;
            float v3 = acc[mf][nf][3] + b1;
            if (EPI == 1) {
                v0 = gelu_exact(v0); v1 = gelu_exact(v1);
                v2 = gelu_exact(v2); v3 = gelu_exact(v3);
            }
            if (EPI == 2) {
                float2 r0v = *(const float2*)(resid + (size_t)row0 * N + col);
                float2 r1v = *(const float2*)(resid + (size_t)row1 * N + col);
                v0 += r0v.x; v1 += r0v.y; v2 += r1v.x; v3 += r1v.y;
            }
            *(float2*)(C + (size_t)row0 * N + col) = make_float2(v0, v1);
            *(float2*)(C + (size_t)row1 * N + col) = make_float2(v2, v3);
        }
    }
}

// ---------------------------------------------------------------------------
// TF32 GEMM n64 variant (R15): 128x64 CTA tile for the N=1024 GEMMs.
// ---------------------------------------------------------------------------
#define BS2_STRIDE 72
#define BS2_FLOATS (32 * BS2_STRIDE)                 // 2304
#define STG2_FLOATS (AS_FLOATS + BS2_FLOATS)         // 6912
#define GEMM64_SMEM_BYTES (2 * STG2_FLOATS * 4)      // 55296

template<int EPI>
__global__ void __launch_bounds__(128, 4) gemm_tf32_n64_kernel(
        const float* __restrict__ A, const float* __restrict__ B,
        const float* __restrict__ bias, const float* __restrict__ resid,
        float* __restrict__ C, int M, int N, int K) {
    extern __shared__ float smem[];
    const uint32_t smem_u32 = (uint32_t)__cvta_generic_to_shared(smem);

    const int bm = blockIdx.y * 128;
    const int bn = blockIdx.x * 64;
    const int tid  = threadIdx.x;
    const int warp = tid >> 5;
    const int lane = tid & 31;
    const int g    = lane >> 2;
    const int tig  = lane & 3;
    const int warp_m = (warp & 1) * 64;
    const int warp_n = (warp >> 1) * 32;

    const uint32_t aoff = (uint32_t)((warp_m + (lane & 15)) * AS_STRIDE * 4)
                        + ((lane & 16) ? 16u : 0u);

    float acc[4][4][4];
    #pragma unroll
    for (int mf = 0; mf < 4; mf++)
        #pragma unroll
        for (int nf = 0; nf < 4; nf++)
            #pragma unroll
            for (int r = 0; r < 4; r++) acc[mf][nf][r] = 0.0f;

    const int NK = K >> 5;

    auto load_tile = [&](int kt) {
        float* As = smem + (kt & 1) * STG2_FLOATS;
        float* Bs = As + AS_FLOATS;
        const int k0 = kt << 5;
        #pragma unroll
        for (int i = 0; i < 8; i++) {
            int f = tid + 128 * i;
            int row = f >> 3, c4 = (f & 7) << 2;
            cp_async16(&As[row * AS_STRIDE + c4],
                       A + (size_t)(bm + row) * K + k0 + c4);
        }
        #pragma unroll
        for (int i = 0; i < 4; i++) {
            int f = tid + 128 * i;
            int row = f >> 4, c4 = (f & 15) << 2;
            cp_async16(&Bs[row * BS2_STRIDE + c4],
                       B + (size_t)(k0 + row) * N + bn + c4);
        }
        cp_async_commit();
    };

    load_tile(0);
    load_tile(1);

    for (int kt = 0; kt < NK; kt++) {
        if (kt + 1 < NK) cp_async_wait<1>();
        else             cp_async_wait<0>();
        __syncthreads();

        const uint32_t As_u32 = smem_u32 + (kt & 1) * (STG2_FLOATS * 4);
        const float* Bs = smem + (kt & 1) * STG2_FLOATS + AS_FLOATS;

        #pragma unroll
        for (int ks = 0; ks < 4; ks++) {
            const int kk = ks << 3;
            uint32_t afrag[4][4];
            #pragma unroll
            for (int mf = 0; mf < 4; mf++)
                ldsm_x4(afrag[mf], As_u32 + aoff + mf * (16 * AS_STRIDE * 4) + ks * 32);
            uint32_t bfrag[4][2];
            #pragma unroll
            for (int nf = 0; nf < 4; nf++) {
                const int c0 = warp_n + nf * 8 + g;
                bfrag[nf][0] = __float_as_uint(Bs[(kk + tig    ) * BS2_STRIDE + c0]);
                bfrag[nf][1] = __float_as_uint(Bs[(kk + tig + 4) * BS2_STRIDE + c0]);
            }
            #pragma unroll
            for (int mf = 0; mf < 4; mf++)
                #pragma unroll
                for (int nf = 0; nf < 4; nf++)
                    mma_tf32(acc[mf][nf], afrag[mf], bfrag[nf]);
        }

        __syncthreads();
        if (kt + 2 < NK) load_tile(kt + 2);
    }

    #pragma unroll
    for (int mf = 0; mf < 4; mf++) {
        #pragma unroll
        for (int nf = 0; nf < 4; nf++) {
            const int row0 = bm + warp_m + mf * 16 + g;
            const int row1 = row0 + 8;
            const int col  = bn + warp_n + nf * 8 + 2 * tig;
            const float b0 = bias[col], b1 = bias[col + 1];
            float v0 = acc[mf][nf][0] + b0;
            float v1 = acc[mf][nf][1] + b1;
            float v2 = acc[mf][nf][2] + b0;
            float v3 = acc[mf][nf][3] + b1;
            if (EPI == 1) {
                v0 = gelu_exact(v0); v1 = gelu_exact(v1);
                v2 = gelu_exact(v2); v3 = gelu_exact(v3);
            }
            if (EPI == 2) {
                float2 r0v = *(const float2*)(resid + (size_t)row0 * N + col);
                float2 r1v = *(const float2*)(resid + (size_t)row1 * N + col);
                v0 += r0v.x; v1 += r0v.y; v2 += r1v.x; v3 += r1v.y;
            }
            *(float2*)(C + (size_t)row0 * N + col) = make_float2(v0, v1);
            *(float2*)(C + (size_t)row1 * N + col) = make_float2(v2, v3);
        }
    }
}

// ---------------------------------------------------------------------------
// Tensor-core masked flash attention v6 (R12/R15 proven).
// ---------------------------------------------------------------------------
#define QT 64
#define CH 64
#define O_QS  0                        // [64][68]
#define O_KS  4352                     // 2 x [64][68]
#define O_VS  13056                    // 2 x [64][72]
#define O_PS  22272                    // [64][68]
#define O_RED 26624                    // [64][2]
#define O_M   26752                    // [64]
#define O_L   26816                    // [64]
#define O_SC  26880                    // [64]
#define ATTN_SMEM_FLOATS 26944
#define ATTN_SMEM_BYTES (ATTN_SMEM_FLOATS * 4)   // 107776

__global__ void __launch_bounds__(256) attn_kernel(
        const float* __restrict__ QKV, float* __restrict__ O) {
    extern __shared__ float dyn[];
    float* Qs  = dyn + O_QS;
    float* Ks  = dyn + O_KS;
    float* Vs  = dyn + O_VS;
    float* Ps  = dyn + O_PS;
    float* red = dyn + O_RED;
    float* mS  = dyn + O_M;
    float* lS  = dyn + O_L;
    float* scS = dyn + O_SC;
    const uint32_t dyn_u32 = (uint32_t)__cvta_generic_to_shared(dyn);

    const int qbase = blockIdx.x * QT;
    const int h  = blockIdx.y;
    const int b  = blockIdx.z;
    const int tid = threadIdx.x;
    const int warp = tid >> 5, lane = tid & 31;
    const int g = lane >> 2, tig = lane & 3;
    const int m0 = (warp >> 1) * 16;
    const int n0 = (warp & 1) * 32;
    const int w2 = warp & 1;
    const int pairbar = (warp >> 1) + 1;

    #define PAIR_BAR() asm volatile("bar.sync %0, 64;" :: "r"(pairbar) : "memory")

    const int RS = 3 * DD;
    const uint32_t qoff = (uint32_t)((m0 + (lane & 15)) * 68 * 4)
                        + ((lane & 16) ? 16u : 0u);
    const uint32_t koff = (uint32_t)((n0 + (lane & 7)) * 68 * 4)
                        + ((lane & 8) ? 16u : 0u)
                        + ((lane & 16) ? (uint32_t)(8 * 68 * 4) : 0u);
    const uint32_t Ps_u32 = dyn_u32 + O_PS * 4;

    int clo = max(0, (qbase - WINDOW) >> 6);
    int chi = min(SS / CH - 1, (qbase + QT - 1 + WINDOW) >> 6);
    if (qbase < NGLOBAL) { clo = 0; chi = SS / CH - 1; }

    auto load_kv = [&](int cc, int bf) {
        const int r = tid >> 4, d4 = tid & 15;
        float* Kb = Ks + bf * 4352;
        float* Vb = Vs + bf * 4608;
        #pragma unroll
        for (int it = 0; it < 4; it++) {
            int rr = r + it * 16;
            const float* src = QKV + (size_t)(b * SS + CH * cc + rr) * RS + h * DKK + d4 * 4;
            cp_async16(Kb + rr * 68 + d4 * 4, src + DD);
            cp_async16(Vb + rr * 72 + d4 * 4, src + 2 * DD);
        }
        cp_async_commit();
    };

    {
        const int r = tid >> 4, d4 = tid & 15;
        #pragma unroll
        for (int it = 0; it < 4; it++) {
            int qi = r + it * 16;
            cp_async16(Qs + qi * 68 + d4 * 4,
                       QKV + (size_t)(b * SS + qbase + qi) * RS + h * DKK + d4 * 4);
        }
        cp_async_commit();
    }
    load_kv(0, 0);

    if (tid < QT) { mS[tid] = -INFINITY; lS[tid] = 0.0f; }

    float o_acc[4][4];
    #pragma unroll
    for (int nf = 0; nf < 4; nf++)
        #pragma unroll
        for (int r = 0; r < 4; r++) o_acc[nf][r] = 0.0f;

    const int i0 = qbase + m0 + g;
    const int i1 = i0 + 8;
    const bool gi0 = (i0 < NGLOBAL);
    const bool gi1 = (i1 < NGLOBAL);

    int c = 0, buf = 0;
    while (c >= 0) {
        int nc;
        if (c == 0) nc = (clo > 0) ? clo : (chi >= 1 ? 1 : -1);
        else        nc = (c + 1 <= chi) ? c + 1 : -1;

        if (nc >= 0) {
            load_kv(nc, buf ^ 1);
            cp_async_wait<1>();
        } else {
            cp_async_wait<0>();
        }
        __syncthreads();

        const uint32_t Kb_u32 = dyn_u32 + (O_KS + buf * 4352) * 4;
        const float* Vb = Vs + buf * 4608;

        float s[4][4];
        #pragma unroll
        for (int nf = 0; nf < 4; nf++)
            #pragma unroll
            for (int r = 0; r < 4; r++) s[nf][r] = 0.0f;
        #pragma unroll
        for (int ks = 0; ks < 8; ks++) {
            uint32_t a[4];
            ldsm_x4(a, dyn_u32 + qoff + ks * 32);
            #pragma unroll
            for (int np = 0; np < 2; np++) {
                uint32_t bb4[4];
                ldsm_x4(bb4, Kb_u32 + koff + np * (16 * 68 * 4) + ks * 32);
                mma_tf32(s[2 * np    ], a, bb4    );
                mma_tf32(s[2 * np + 1], a, bb4 + 2);
            }
        }

        float mx0 = -INFINITY, mx1 = -INFINITY;
        #pragma unroll
        for (int nf = 0; nf < 4; nf++) {
            const int j0 = CH * c + n0 + nf * 8 + 2 * tig;
            const int j1 = j0 + 1;
            const bool vj0 = (j0 < NGLOBAL), vj1 = (j1 < NGLOBAL);
            s[nf][0] = (gi0 || vj0 || abs(i0 - j0) <= WINDOW) ? s[nf][0] * 0.125f : -INFINITY;
            s[nf][1] = (gi0 || vj1 || abs(i0 - j1) <= WINDOW) ? s[nf][1] * 0.125f : -INFINITY;
            s[nf][2] = (gi1 || vj0 || abs(i1 - j0) <= WINDOW) ? s[nf][2] * 0.125f : -INFINITY;
            s[nf][3] = (gi1 || vj1 || abs(i1 - j1) <= WINDOW) ? s[nf][3] * 0.125f : -INFINITY;
            mx0 = fmaxf(mx0, fmaxf(s[nf][0], s[nf][1]));
            mx1 = fmaxf(mx1, fmaxf(s[nf][2], s[nf][3]));
        }
        mx0 = fmaxf(mx0, __shfl_xor_sync(0xffffffffu, mx0, 1));
        mx0 = fmaxf(mx0, __shfl_xor_sync(0xffffffffu, mx0, 2));
        mx1 = fmaxf(mx1, __shfl_xor_sync(0xffffffffu, mx1, 1));
        mx1 = fmaxf(mx1, __shfl_xor_sync(0xffffffffu, mx1, 2));
        if (tig == 0) {
            red[(m0 + g    ) * 2 + w2] = mx0;
            red[(m0 + g + 8) * 2 + w2] = mx1;
        }
        PAIR_BAR();

        if (w2 == 0 && tig == 0) {
            const int r0 = m0 + g, r1 = m0 + g + 8;
            float mn0 = fmaxf(fmaxf(red[r0 * 2], red[r0 * 2 + 1]), mS[r0]);
            scS[r0] = __expf(mS[r0] - mn0);
            mS[r0]  = mn0;
            float mn1 = fmaxf(fmaxf(red[r1 * 2], red[r1 * 2 + 1]), mS[r1]);
            scS[r1] = __expf(mS[r1] - mn1);
            mS[r1]  = mn1;
        }
        PAIR_BAR();

        const float m0v = mS[m0 + g], m1v = mS[m0 + g + 8];
        float sum0 = 0.0f, sum1 = 0.0f;
        #pragma unroll
        for (int nf = 0; nf < 4; nf++) {
            s[nf][0] = __expf(s[nf][0] - m0v);
            s[nf][1] = __expf(s[nf][1] - m0v);
            s[nf][2] = __expf(s[nf][2] - m1v);
            s[nf][3] = __expf(s[nf][3] - m1v);
            sum0 += s[nf][0] + s[nf][1];
            sum1 += s[nf][2] + s[nf][3];
            const int col = n0 + nf * 8 + 2 * tig;
            *(float2*)&Ps[(m0 + g    ) * 68 + col] = make_float2(s[nf][0], s[nf][1]);
            *(float2*)&Ps[(m0 + g + 8) * 68 + col] = make_float2(s[nf][2], s[nf][3]);
        }
        sum0 += __shfl_xor_sync(0xffffffffu, sum0, 1);
        sum0 += __shfl_xor_sync(0xffffffffu, sum0, 2);
        sum1 += __shfl_xor_sync(0xffffffffu, sum1, 1);
        sum1 += __shfl_xor_sync(0xffffffffu, sum1, 2);
        if (tig == 0) {
            red[(m0 + g    ) * 2 + w2] = sum0;
            red[(m0 + g + 8) * 2 + w2] = sum1;
        }
        {
            const float sc0 = scS[m0 + g], sc1 = scS[m0 + g + 8];
            #pragma unroll
            for (int nf = 0; nf < 4; nf++) {
                o_acc[nf][0] *= sc0; o_acc[nf][1] *= sc0;
                o_acc[nf][2] *= sc1; o_acc[nf][3] *= sc1;
            }
        }
        PAIR_BAR();

        if (w2 == 0 && tig == 0) {
            const int r0 = m0 + g, r1 = m0 + g + 8;
            lS[r0] = lS[r0] * scS[r0] + red[r0 * 2] + red[r0 * 2 + 1];
            lS[r1] = lS[r1] * scS[r1] + red[r1 * 2] + red[r1 * 2 + 1];
        }

        #pragma unroll
        for (int ks = 0; ks < 8; ks++) {
            const int kk = ks << 3;
            uint32_t a[4];
            ldsm_x4(a, Ps_u32 + qoff + ks * 32);
            #pragma unroll
            for (int nf = 0; nf < 4; nf++) {
                uint32_t bb[2];
                bb[0] = __float_as_uint(Vb[(kk + tig    ) * 72 + n0 + nf * 8 + g]);
                bb[1] = __float_as_uint(Vb[(kk + tig + 4) * 72 + n0 + nf * 8 + g]);
                mma_tf32(o_acc[nf], a, bb);
            }
        }

        __syncthreads();

        c = nc;
        buf ^= 1;
    }

    const float inv0 = 1.0f / lS[m0 + g];
    const float inv1 = 1.0f / lS[m0 + g + 8];
    #pragma unroll
    for (int nf = 0; nf < 4; nf++) {
        const int col = h * DKK + n0 + nf * 8 + 2 * tig;
        float* o0 = O + (size_t)(b * SS + qbase + m0 + g    ) * DD + col;
        float* o1 = O + (size_t)(b * SS + qbase + m0 + g + 8) * DD + col;
        *(float2*)o0 = make_float2(o_acc[nf][0] * inv0, o_acc[nf][1] * inv0);
        *(float2*)o1 = make_float2(o_acc[nf][2] * inv1, o_acc[nf][3] * inv1);
    }
    #undef PAIR_BAR
}

// ---------------------------------------------------------------------------
// Launch
// ---------------------------------------------------------------------------
extern "C" void kernel_launch(void* const* d_in, const int* in_sizes, int n_in,
                              void* d_out, int out_size) {
    const float* x     = (const float*)d_in[0];
    const float* Wq    = (const float*)d_in[1];
    const float* bq    = (const float*)d_in[2];
    const float* Wk    = (const float*)d_in[3];
    const float* bk    = (const float*)d_in[4];
    const float* Wv    = (const float*)d_in[5];
    const float* bv    = (const float*)d_in[6];
    const float* Wo    = (const float*)d_in[7];
    const float* bo    = (const float*)d_in[8];
    const float* ln1_g = (const float*)d_in[9];
    const float* ln1_b = (const float*)d_in[10];
    const float* W1    = (const float*)d_in[11];
    const float* b1    = (const float*)d_in[12];
    const float* W2    = (const float*)d_in[13];
    const float* b2    = (const float*)d_in[14];
    const float* ln2_g = (const float*)d_in[15];
    const float* ln2_b = (const float*)d_in[16];
    float* out = (float*)d_out;

    float *xn, *qkv, *att, *x1, *xn2, *hbuf, *wqkv, *bqkv;
    cudaGetSymbolAddress((void**)&xn,   g_xn);
    cudaGetSymbolAddress((void**)&qkv,  g_qkv);
    cudaGetSymbolAddress((void**)&att,  g_att);
    cudaGetSymbolAddress((void**)&x1,   g_x1);
    cudaGetSymbolAddress((void**)&xn2,  g_xn2);
    cudaGetSymbolAddress((void**)&hbuf, g_h);
    cudaGetSymbolAddress((void**)&wqkv, g_wqkv);
    cudaGetSymbolAddress((void**)&bqkv, g_bqkv);

    cudaFuncSetAttribute(gemm_tf32_kernel<0>,
        cudaFuncAttributeMaxDynamicSharedMemorySize, GEMM_SMEM_BYTES);
    cudaFuncSetAttribute(gemm_tf32_kernel<1>,
        cudaFuncAttributeMaxDynamicSharedMemorySize, GEMM_SMEM_BYTES);
    cudaFuncSetAttribute(gemm_tf32_n64_kernel<2>,
        cudaFuncAttributeMaxDynamicSharedMemorySize, GEMM64_SMEM_BYTES);
    cudaFuncSetAttribute(attn_kernel,
        cudaFuncAttributeMaxDynamicSharedMemorySize, ATTN_SMEM_BYTES);

    // 0) prepass: QKV weight/bias concat only (raw copy; mma truncates)
    prep_kernel<<<(PREP_TOTAL + 255) / 256, 256>>>(
        (const float4*)Wq, (const float4*)Wk, (const float4*)Wv,
        (const float4*)bq, (const float4*)bk, (const float4*)bv,
        (float4*)wqkv, (float4*)bqkv);

    // 1) xn = LN(x)
    ln_kernel<<<MM, 256>>>(x, ln1_g, ln1_b, xn);

    // 2) qkv = xn @ Wqkv + bqkv
    dim3 gq(3 * DD / 128, MM / 128);
    gemm_tf32_kernel<0><<<gq, 128, GEMM_SMEM_BYTES>>>(xn, wqkv, bqkv, nullptr,
                                                      qkv, MM, 3 * DD, DD);

    // 3) tensor-core masked attention
    attn_kernel<<<dim3(SS / QT, HH, BB), 256, ATTN_SMEM_BYTES>>>(qkv, att);

    // 4) x1 = x + att @ Wo + bo   (Wo/bo direct from inputs)
    dim3 g64(DD / 64, MM / 128);
    gemm_tf32_n64_kernel<2><<<g64, 128, GEMM64_SMEM_BYTES>>>(att, Wo, bo, x, x1, MM, DD, DD);

    // 5) xn2 = LN(x1)
    ln_kernel<<<MM, 256>>>(x1, ln2_g, ln2_b, xn2);

    // 6) h = gelu(xn2 @ W1 + b1)  (W1/b1 direct)
    dim3 g2(DFF / 128, MM / 128);
    gemm_tf32_kernel<1><<<g2, 128, GEMM_SMEM_BYTES>>>(xn2, W1, b1, nullptr, hbuf, MM, DFF, DD);

    // 7) out = x1 + h @ W2 + b2   (W2/b2 direct)
    gemm_tf32_n64_kernel<2><<<g64, 128, GEMM64_SMEM_BYTES>>>(hbuf, W2, b2, x1, out, MM, DD, DFF);
}